// round 12
// baseline (speedup 1.0000x reference)
#include <cuda_runtime.h>
#include <cuda_fp16.h>

#define NPTS 32768
#define CH   128
#define NT   256

// ======================= baseline-PTX helpers =======================
__device__ __forceinline__ unsigned smem_to_u32(const void* p) {
    unsigned a;
    asm("{ .reg .u64 t; cvta.to.shared.u64 t, %1; cvt.u32.u64 %0, t; }" : "=r"(a) : "l"(p));
    return a;
}
__device__ __forceinline__ void cp16(unsigned dst, const void* src) {
    asm volatile("cp.async.cg.shared.global [%0], [%1], 16;" :: "r"(dst), "l"(src));
}
#define CP_COMMIT() asm volatile("cp.async.commit_group;" ::: "memory")
#define CP_WAIT(n)  asm volatile("cp.async.wait_group %0;" :: "n"(n) : "memory")

__device__ __forceinline__ void ldsm_x4(unsigned* r, unsigned addr) {
    asm volatile("ldmatrix.sync.aligned.m8n8.x4.shared.b16 {%0,%1,%2,%3}, [%4];"
        : "=r"(r[0]), "=r"(r[1]), "=r"(r[2]), "=r"(r[3]) : "r"(addr));
}
__device__ __forceinline__ void ldsm_x4_t(unsigned* r, unsigned addr) {
    asm volatile("ldmatrix.sync.aligned.m8n8.x4.trans.shared.b16 {%0,%1,%2,%3}, [%4];"
        : "=r"(r[0]), "=r"(r[1]), "=r"(r[2]), "=r"(r[3]) : "r"(addr));
}
__device__ __forceinline__ void mma16816(float* c, const unsigned* a, unsigned b0, unsigned b1) {
    asm volatile("mma.sync.aligned.m16n8k16.row.col.f32.f16.f16.f32 "
        "{%0,%1,%2,%3}, {%4,%5,%6,%7}, {%8,%9}, {%0,%1,%2,%3};"
        : "+f"(c[0]), "+f"(c[1]), "+f"(c[2]), "+f"(c[3])
        : "r"(a[0]), "r"(a[1]), "r"(a[2]), "r"(a[3]), "r"(b0), "r"(b1));
}

// ======================= tconv sizes (full-tap stages, M=256, 8 warps) =====
#define MROWS  256
#define ROWB   272                     // padded row stride (16B-aligned, ldsm-safe)
#define ABUF   (MROWS*ROWB)            // 69632
#define BBUF   (128*ROWB)              // 34816
#define STG    (ABUF + BBUF)           // 104448
#define TCONV_SMEM (2*STG)             // 208896 (1 CTA/SM)

// ======================= scratch =======================
__device__ __align__(16) float  g_V [NPTS*CH];
__device__ __align__(16) float  g_Y [NPTS*CH];
__device__ __align__(16) float  g_R [NPTS*CH];
__device__ __align__(16) __half g_Ah[NPTS*CH];
__device__ __align__(16) __half g_Gh[NPTS*CH];
__device__ __align__(16) __half g_Th[NPTS*CH];
__device__ __align__(16) __half g_W5b [125*CH*CH];   // fp16 [k][ci][co]
__device__ __align__(16) __half g_W31b[27*CH*CH];
__device__ __align__(16) __half g_W32b[27*CH*CH];
__device__ int g_nT5 [125*NPTS];
__device__ int g_nT3a[27*NPTS];
__device__ int g_nT3b[27*NPTS];
__device__ __align__(16) float g_part[2*64*256];
__device__ __align__(16) float g_scale[CH];
__device__ __align__(16) float g_shift[CH];

// ======================= prep kernels (fused) =======================
__global__ void wprep_all(const float* __restrict__ W5, const float* __restrict__ W31,
                          const float* __restrict__ W32,
                          __half* __restrict__ o5, __half* __restrict__ o31,
                          __half* __restrict__ o32)
{
    int b = blockIdx.x;                 // 179*64 blocks
    const float* W; __half* O; int kb;
    if (b < 125*64)      { W = W5;  O = o5;  kb = b; }
    else if (b < 152*64) { W = W31; O = o31; kb = b - 125*64; }
    else                 { W = W32; O = o32; kb = b - 152*64; }
    int e = kb * 256 + threadIdx.x;
    O[e] = __float2half_rn(W[e]);
}

__global__ void ntr_all(const int* __restrict__ nbr5, const int* __restrict__ nbr3a,
                        const int* __restrict__ nbr3b,
                        int* __restrict__ n5, int* __restrict__ n3a, int* __restrict__ n3b)
{
    __shared__ int t[32][33];
    int bx = blockIdx.x;
    const int* src; int* dst; int K, k0;
    if (bx < 4)       { src = nbr5;  dst = n5;  K = 125; k0 = bx*32; }
    else if (bx == 4) { src = nbr3a; dst = n3a; K = 27;  k0 = 0; }
    else              { src = nbr3b; dst = n3b; K = 27;  k0 = 0; }
    int i0 = blockIdx.y * 32;
    int tx = threadIdx.x & 31, ty = threadIdx.x >> 5;
#pragma unroll
    for (int r = 0; r < 32; r += 8) {
        int kk = k0 + tx;
        t[ty + r][tx] = (kk < K) ? src[(size_t)(i0 + ty + r) * K + kk] : 0;
    }
    __syncthreads();
#pragma unroll
    for (int r = 0; r < 32; r += 8) {
        int kk = k0 + ty + r;
        if (kk < K) dst[(size_t)kk * NPTS + i0 + tx] = t[tx][ty + r];
    }
}

// ======================= HMMA gather-conv ====================================
// R7 skeleton (depth-2 prefetch, 2 syncs/tap) + register idx prefetch.
// A gather: one row per thread, idx passed in a register (no LDG in burst).
__device__ __forceinline__ void issue_tap(
    unsigned smem, int buf, int tap,
    const __half* feats, const __half* Wb, int idx, int tid)
{
    const unsigned Ab = smem + (unsigned)buf*STG;
    const unsigned Bb = Ab + ABUF;
    // A: thread t -> row t (256 rows), 16 chunks of 16B
    const char* src = (const char*)(feats + (size_t)idx*CH);
    unsigned dst = Ab + (unsigned)tid*ROWB;
#pragma unroll
    for (int j = 0; j < 16; ++j)
        cp16(dst + (unsigned)j*16u, src + j*16);
    // B: 128 rows x 256B, coalesced (16 lanes per row)
    const char* wsrc = (const char*)(Wb + (size_t)tap*(CH*CH));
#pragma unroll
    for (int j = 0; j < 8; ++j) {
        int lin = tid + 256*j;
        int row = lin >> 4;
        int c   = lin & 15;
        cp16(Bb + (unsigned)row*ROWB + (unsigned)c*16u, wsrc + (size_t)row*256 + c*16);
    }
}

__global__ void __launch_bounds__(NT, 1)
tconv_kernel(const __half* __restrict__ feats,
             const __half* __restrict__ Wb,     // [K][128][128] fp16
             const int*    __restrict__ nbrT,   // [K][NPTS] or null
             const int K,
             const float*  __restrict__ gate,   // fp32 or null
             __half* __restrict__ out16,        // or null
             float*  __restrict__ out32)        // or null
{
    extern __shared__ char dsm[];
    const int tid  = threadIdx.x;
    const int lane = tid & 31;
    const int w    = tid >> 5;          // 0..7
    const int row0 = blockIdx.x * MROWS;
    const int m0   = (w >> 1) * 64;     // 4 m-groups of 64 rows
    const int n0   = (w & 1) * 64;      // 2 n-groups of 64 cols
    const unsigned smem = smem_to_u32(dsm);

    // prologue: taps 0,1 with synchronous idx loads (one-time cost)
    {
        int idx0 = nbrT ? nbrT[row0 + tid] : (row0 + tid);
        issue_tap(smem, 0, 0, feats, Wb, idx0, tid);
        CP_COMMIT();
        if (K > 1) {
            int idx1 = nbrT ? nbrT[(size_t)NPTS + row0 + tid] : (row0 + tid);
            issue_tap(smem, 1, 1, feats, Wb, idx1, tid);
            CP_COMMIT();
        }
    }
    // idx for tap 2, prefetched into a register
    int idxN = (nbrT && K > 2) ? nbrT[2*(size_t)NPTS + row0 + tid] : (row0 + tid);

    float acc[4][8][4];
#pragma unroll
    for (int i = 0; i < 4; ++i)
#pragma unroll
        for (int j = 0; j < 8; ++j)
#pragma unroll
            for (int e = 0; e < 4; ++e) acc[i][j][e] = 0.f;

    const unsigned lane_off = (unsigned)(lane & 15) * ROWB + (unsigned)(lane >> 4) * 16u;

    for (int k = 0; k < K; ++k) {
        const int buf = k & 1;
        if (k + 1 < K) { CP_WAIT(1); } else { CP_WAIT(0); }
        __syncthreads();   // tap k data visible to all warps

        const unsigned Ab = smem + (unsigned)buf*STG;
        const unsigned Bb = Ab + ABUF;

#pragma unroll
        for (int ks = 0; ks < 8; ++ks) {
            unsigned a[4][4];
            unsigned abase = Ab + (unsigned)m0*ROWB + (unsigned)ks*32u + lane_off;
#pragma unroll
            for (int q = 0; q < 4; ++q) ldsm_x4(a[q], abase + (unsigned)q*16u*ROWB);
            unsigned bbase = Bb + (unsigned)ks*16u*ROWB + (unsigned)n0*2u + lane_off;
            unsigned b[4][4];
#pragma unroll
            for (int p = 0; p < 4; ++p) ldsm_x4_t(b[p], bbase + (unsigned)p*32u);
#pragma unroll
            for (int p = 0; p < 4; ++p) {
#pragma unroll
                for (int q = 0; q < 4; ++q) {
                    mma16816(acc[q][2*p],   a[q], b[p][0], b[p][1]);
                    mma16816(acc[q][2*p+1], a[q], b[p][2], b[p][3]);
                }
            }
        }

        __syncthreads();   // all warps done reading buf before refill

        if (k + 2 < K) {
            // pure cp.async burst — idx already in a register
            issue_tap(smem, buf, k + 2, feats, Wb, idxN, tid);
            CP_COMMIT();
            if (k + 3 < K)
                idxN = nbrT ? nbrT[(size_t)(k + 3)*NPTS + row0 + tid] : (row0 + tid);
        }
    }

    // epilogue (optional fp32 gate fused)
#pragma unroll
    for (int msub = 0; msub < 4; ++msub) {
#pragma unroll
        for (int nb = 0; nb < 8; ++nb) {
#pragma unroll
            for (int ep = 0; ep < 2; ++ep) {
                int row = row0 + m0 + msub*16 + (lane >> 2) + ep*8;
                int col = n0 + nb*8 + (lane & 3)*2;
                float v0 = acc[msub][nb][ep*2];
                float v1 = acc[msub][nb][ep*2 + 1];
                size_t off = (size_t)row * CH + col;
                if (gate) {
                    float2 g = *reinterpret_cast<const float2*>(gate + off);
                    v0 *= g.x; v1 *= g.y;
                }
                if (out32) *reinterpret_cast<float2*>(out32 + off) = make_float2(v0, v1);
                if (out16) *reinterpret_cast<__half2*>(out16 + off) = __floats2half2_rn(v0, v1);
            }
        }
    }
}

// ======================= SIMT 1x1 GEMMs, both in one launch =================
#define TM 128
#define KC 32
#define SMEM_FLOATS (TM*CH + KC*CH + TM)
#define SMEM_BYTES  (SMEM_FLOATS * 4)
__global__ void __launch_bounds__(NT, 2)
sconv_av(const float* __restrict__ x,
         const float* __restrict__ Wa1, const float* __restrict__ Wv1,
         __half* __restrict__ Ah, float* __restrict__ V)
{
    extern __shared__ float smem[];
    float* Fs = smem;
    float* Ws = smem + TM*CH;
    const int tid = threadIdx.x;
    const bool isA = blockIdx.x < (NPTS/TM);
    const int row0 = (isA ? blockIdx.x : blockIdx.x - NPTS/TM) * TM;
    const float* Wt = isA ? Wa1 : Wv1;
    const int tcx = tid & 15, tcy = tid >> 4;
    float acc[8][8];
#pragma unroll
    for (int r = 0; r < 8; ++r)
#pragma unroll
        for (int c = 0; c < 8; ++c) acc[r][c] = 0.f;

#pragma unroll
    for (int j = 0; j < (TM*CH/4)/NT; ++j) {
        int lin = tid + j*NT;
        int r = lin >> 5, c4 = lin & 31;
        reinterpret_cast<float4*>(Fs + r*CH)[c4] =
            reinterpret_cast<const float4*>(x + (size_t)(row0 + r)*CH)[c4];
    }
#pragma unroll 1
    for (int cc = 0; cc < CH/KC; ++cc) {
        __syncthreads();
#pragma unroll
        for (int j = 0; j < 4; ++j) {
            int lin = tid + j*NT;
            reinterpret_cast<float4*>(Ws)[lin] =
                reinterpret_cast<const float4*>(Wt + cc*(KC*CH))[lin];
        }
        __syncthreads();
        const float* fp = Fs + (tcy*8)*CH + cc*KC;
        const float4* wrow = reinterpret_cast<const float4*>(Ws);
#pragma unroll 4
        for (int ci = 0; ci < KC; ++ci) {
            float f[8];
#pragma unroll
            for (int r = 0; r < 8; ++r) f[r] = fp[r*CH + ci];
            float4 w0 = wrow[ci*(CH/4) + tcx*2];
            float4 w1 = wrow[ci*(CH/4) + tcx*2 + 1];
            float wv[8] = {w0.x, w0.y, w0.z, w0.w, w1.x, w1.y, w1.z, w1.w};
#pragma unroll
            for (int r = 0; r < 8; ++r)
#pragma unroll
                for (int c = 0; c < 8; ++c)
                    acc[r][c] = fmaf(f[r], wv[c], acc[r][c]);
        }
    }
#pragma unroll
    for (int r = 0; r < 8; ++r) {
        size_t base = (size_t)(row0 + tcy*8 + r)*CH + tcx*8;
        if (isA) {
            __half2* hp = reinterpret_cast<__half2*>(Ah + base);
            hp[0] = __floats2half2_rn(acc[r][0], acc[r][1]);
            hp[1] = __floats2half2_rn(acc[r][2], acc[r][3]);
            hp[2] = __floats2half2_rn(acc[r][4], acc[r][5]);
            hp[3] = __floats2half2_rn(acc[r][6], acc[r][7]);
        } else {
            *reinterpret_cast<float4*>(V + base)     = make_float4(acc[r][0],acc[r][1],acc[r][2],acc[r][3]);
            *reinterpret_cast<float4*>(V + base + 4) = make_float4(acc[r][4],acc[r][5],acc[r][6],acc[r][7]);
        }
    }
}

// ======================= BN / elementwise =======================
__global__ void bn_partial_kernel(const float* __restrict__ y)
{
    int tid = threadIdx.x;
    int c = tid & (CH-1), half = tid >> 7;
    int rbase = blockIdx.x * 512 + half;
    float s = 0.f, s2 = 0.f;
#pragma unroll 8
    for (int j = 0; j < 256; ++j) {
        float v = y[(size_t)(rbase + 2*j)*CH + c];
        s += v; s2 = fmaf(v, v, s2);
    }
    g_part[blockIdx.x*256 + tid]          = s;
    g_part[64*256 + blockIdx.x*256 + tid] = s2;
}
__global__ void bn_finalize_kernel(const float* __restrict__ gamma, const float* __restrict__ beta)
{
    int c = threadIdx.x;
    float s = 0.f, s2 = 0.f;
    for (int b = 0; b < 64; ++b) {
        s  += g_part[b*256 + c] + g_part[b*256 + CH + c];
        s2 += g_part[64*256 + b*256 + c] + g_part[64*256 + b*256 + CH + c];
    }
    const float inv = 1.0f / (float)NPTS;
    float mu = s * inv;
    float var = s2 * inv - mu*mu;
    float sc = gamma[c] * rsqrtf(var + 1e-5f);
    g_scale[c] = sc;
    g_shift[c] = fmaf(-mu, sc, beta[c]);
}
__global__ void ew1_kernel(const float* __restrict__ y, const float* __restrict__ x)
{
    size_t i = (size_t)blockIdx.x * blockDim.x + threadIdx.x;
    float4 yv = reinterpret_cast<const float4*>(y)[i];
    float4 xv = reinterpret_cast<const float4*>(x)[i];
    int cg = (int)(i & 31);
    float4 sc = reinterpret_cast<const float4*>(g_scale)[cg];
    float4 sh = reinterpret_cast<const float4*>(g_shift)[cg];
    float4 r2;
    r2.x = fmaf(yv.x, sc.x, sh.x) + xv.x;
    r2.y = fmaf(yv.y, sc.y, sh.y) + xv.y;
    r2.z = fmaf(yv.z, sc.z, sh.z) + xv.z;
    r2.w = fmaf(yv.w, sc.w, sh.w) + xv.w;
    reinterpret_cast<float4*>(g_R)[i] = r2;
    reinterpret_cast<__half2*>(g_Th)[2*i]   = __floats2half2_rn(fmaxf(r2.x,0.f), fmaxf(r2.y,0.f));
    reinterpret_cast<__half2*>(g_Th)[2*i+1] = __floats2half2_rn(fmaxf(r2.z,0.f), fmaxf(r2.w,0.f));
}
__global__ void ew2_kernel(const float* __restrict__ y, float* __restrict__ out)
{
    size_t i = (size_t)blockIdx.x * blockDim.x + threadIdx.x;
    float4 yv = reinterpret_cast<const float4*>(y)[i];
    float4 rv = reinterpret_cast<const float4*>(g_R)[i];
    int cg = (int)(i & 31);
    float4 sc = reinterpret_cast<const float4*>(g_scale)[cg];
    float4 sh = reinterpret_cast<const float4*>(g_shift)[cg];
    float4 o;
    o.x = fmaxf(fmaf(yv.x, sc.x, sh.x) + rv.x, 0.f);
    o.y = fmaxf(fmaf(yv.y, sc.y, sh.y) + rv.y, 0.f);
    o.z = fmaxf(fmaf(yv.z, sc.z, sh.z) + rv.z, 0.f);
    o.w = fmaxf(fmaf(yv.w, sc.w, sh.w) + rv.w, 0.f);
    reinterpret_cast<float4*>(out)[i] = o;
}

// ======================= launch =======================
extern "C" void kernel_launch(void* const* d_in, const int* in_sizes, int n_in,
                              void* d_out, int out_size)
{
    const float* x      = (const float*)d_in[0];
    const float* Wa1    = (const float*)d_in[1];
    const float* Wv1    = (const float*)d_in[2];
    const float* W5     = (const float*)d_in[3];
    const float* W31    = (const float*)d_in[4];
    const float* W32    = (const float*)d_in[5];
    const float* gamma1 = (const float*)d_in[6];
    const float* beta1  = (const float*)d_in[7];
    const float* gamma2 = (const float*)d_in[8];
    const float* beta2  = (const float*)d_in[9];
    const int*   nbr5   = (const int*)d_in[10];
    const int*   nbr3a  = (const int*)d_in[11];
    const int*   nbr3b  = (const int*)d_in[12];
    float* out = (float*)d_out;

    float *pV, *pY;
    __half *pAh, *pGh, *pTh, *pW5b, *pW31b, *pW32b;
    int *pn5, *pn3a, *pn3b;
    cudaGetSymbolAddress((void**)&pV,  g_V);
    cudaGetSymbolAddress((void**)&pY,  g_Y);
    cudaGetSymbolAddress((void**)&pAh, g_Ah);
    cudaGetSymbolAddress((void**)&pGh, g_Gh);
    cudaGetSymbolAddress((void**)&pTh, g_Th);
    cudaGetSymbolAddress((void**)&pW5b, g_W5b);
    cudaGetSymbolAddress((void**)&pW31b, g_W31b);
    cudaGetSymbolAddress((void**)&pW32b, g_W32b);
    cudaGetSymbolAddress((void**)&pn5,  g_nT5);
    cudaGetSymbolAddress((void**)&pn3a, g_nT3a);
    cudaGetSymbolAddress((void**)&pn3b, g_nT3b);

    cudaFuncSetAttribute(sconv_av, cudaFuncAttributeMaxDynamicSharedMemorySize, SMEM_BYTES);
    cudaFuncSetAttribute(tconv_kernel, cudaFuncAttributeMaxDynamicSharedMemorySize, TCONV_SMEM);

    const int tgrid = NPTS / MROWS;       // 128
    const int ewgrid = (NPTS*CH/4) / 256;

    // 1: weight images   2: neighbor transposes
    wprep_all<<<179*64, 256>>>(W5, W31, W32, pW5b, pW31b, pW32b);
    ntr_all<<<dim3(6, NPTS/32), 256>>>(nbr5, nbr3a, nbr3b, pn5, pn3a, pn3b);
    // 3: a = fp16(x @ Wa1) AND v = fp32(x @ Wv1)
    sconv_av<<<2*(NPTS/TM), NT, SMEM_BYTES>>>(x, Wa1, Wv1, pAh, pV);
    // 4: Gh = fp16( conv5(a) * v )  -- gate fused; ncu captures this launch
    tconv_kernel<<<tgrid, NT, TCONV_SMEM>>>(pAh, pW5b, pn5, 125, pV, pGh, nullptr);
    // 5-8: conv3a -> BN1 -> ew1
    tconv_kernel<<<tgrid, NT, TCONV_SMEM>>>(pGh, pW31b, pn3a, 27, nullptr, nullptr, pY);
    bn_partial_kernel<<<64, 256>>>(pY);
    bn_finalize_kernel<<<1, 128>>>(gamma1, beta1);
    ew1_kernel<<<ewgrid, 256>>>(pY, x);
    // 9-12: conv3b -> BN2 -> ew2
    tconv_kernel<<<tgrid, NT, TCONV_SMEM>>>(pTh, pW32b, pn3b, 27, nullptr, nullptr, pY);
    bn_partial_kernel<<<64, 256>>>(pY);
    bn_finalize_kernel<<<1, 128>>>(gamma2, beta2);
    ew2_kernel<<<ewgrid, 256>>>(pY, out);
}

// round 13
// speedup vs baseline: 1.4694x; 1.4694x over previous
#include <cuda_runtime.h>
#include <cuda_fp16.h>

#define NPTS 32768
#define CH   128
#define NT   256

// ======================= baseline-PTX helpers =======================
__device__ __forceinline__ unsigned smem_to_u32(const void* p) {
    unsigned a;
    asm("{ .reg .u64 t; cvta.to.shared.u64 t, %1; cvt.u32.u64 %0, t; }" : "=r"(a) : "l"(p));
    return a;
}
__device__ __forceinline__ void cp16(unsigned dst, const void* src) {
    asm volatile("cp.async.cg.shared.global [%0], [%1], 16;" :: "r"(dst), "l"(src));
}
#define CP_COMMIT() asm volatile("cp.async.commit_group;" ::: "memory")
#define CP_WAIT(n)  asm volatile("cp.async.wait_group %0;" :: "n"(n) : "memory")

__device__ __forceinline__ void ldsm_x4(unsigned* r, unsigned addr) {
    asm volatile("ldmatrix.sync.aligned.m8n8.x4.shared.b16 {%0,%1,%2,%3}, [%4];"
        : "=r"(r[0]), "=r"(r[1]), "=r"(r[2]), "=r"(r[3]) : "r"(addr));
}
__device__ __forceinline__ void ldsm_x4_t(unsigned* r, unsigned addr) {
    asm volatile("ldmatrix.sync.aligned.m8n8.x4.trans.shared.b16 {%0,%1,%2,%3}, [%4];"
        : "=r"(r[0]), "=r"(r[1]), "=r"(r[2]), "=r"(r[3]) : "r"(addr));
}
__device__ __forceinline__ void mma16816(float* c, const unsigned* a, unsigned b0, unsigned b1) {
    asm volatile("mma.sync.aligned.m16n8k16.row.col.f32.f16.f16.f32 "
        "{%0,%1,%2,%3}, {%4,%5,%6,%7}, {%8,%9}, {%0,%1,%2,%3};"
        : "+f"(c[0]), "+f"(c[1]), "+f"(c[2]), "+f"(c[3])
        : "r"(a[0]), "r"(a[1]), "r"(a[2]), "r"(a[3]), "r"(b0), "r"(b1));
}

// ======================= tconv sizes (full-tap stages, M=256, 8 warps) =====
#define MROWS  256
#define ROWB   272                     // padded row stride (16B-aligned, ldsm-safe)
#define ABUF   (MROWS*ROWB)            // 69632
#define BBUF   (128*ROWB)              // 34816
#define STG    (ABUF + BBUF)           // 104448
#define IDXSZ  1024                    // 256 ints per slot
#define TCONV_SMEM (2*STG + 4*IDXSZ)   // 212992 (1 CTA/SM)

// ======================= scratch =======================
__device__ __align__(16) float  g_V [NPTS*CH];
__device__ __align__(16) float  g_Y [NPTS*CH];
__device__ __align__(16) float  g_R [NPTS*CH];
__device__ __align__(16) __half g_Ah[NPTS*CH];
__device__ __align__(16) __half g_Gh[NPTS*CH];
__device__ __align__(16) __half g_Th[NPTS*CH];
__device__ __align__(16) __half g_W5b [125*CH*CH];   // fp16 [k][ci][co]
__device__ __align__(16) __half g_W31b[27*CH*CH];
__device__ __align__(16) __half g_W32b[27*CH*CH];
__device__ int g_nT5 [125*NPTS];
__device__ int g_nT3a[27*NPTS];
__device__ int g_nT3b[27*NPTS];
__device__ __align__(16) float g_part[2*64*256];
__device__ __align__(16) float g_scale[CH];
__device__ __align__(16) float g_shift[CH];

// ======================= prep kernels (fused) =======================
__global__ void wprep_all(const float* __restrict__ W5, const float* __restrict__ W31,
                          const float* __restrict__ W32,
                          __half* __restrict__ o5, __half* __restrict__ o31,
                          __half* __restrict__ o32)
{
    int b = blockIdx.x;                 // 179*64 blocks
    const float* W; __half* O; int kb;
    if (b < 125*64)      { W = W5;  O = o5;  kb = b; }
    else if (b < 152*64) { W = W31; O = o31; kb = b - 125*64; }
    else                 { W = W32; O = o32; kb = b - 152*64; }
    int e = kb * 256 + threadIdx.x;
    O[e] = __float2half_rn(W[e]);
}

__global__ void ntr_all(const int* __restrict__ nbr5, const int* __restrict__ nbr3a,
                        const int* __restrict__ nbr3b,
                        int* __restrict__ n5, int* __restrict__ n3a, int* __restrict__ n3b)
{
    __shared__ int t[32][33];
    int bx = blockIdx.x;
    const int* src; int* dst; int K, k0;
    if (bx < 4)       { src = nbr5;  dst = n5;  K = 125; k0 = bx*32; }
    else if (bx == 4) { src = nbr3a; dst = n3a; K = 27;  k0 = 0; }
    else              { src = nbr3b; dst = n3b; K = 27;  k0 = 0; }
    int i0 = blockIdx.y * 32;
    int tx = threadIdx.x & 31, ty = threadIdx.x >> 5;
#pragma unroll
    for (int r = 0; r < 32; r += 8) {
        int kk = k0 + tx;
        t[ty + r][tx] = (kk < K) ? src[(size_t)(i0 + ty + r) * K + kk] : 0;
    }
    __syncthreads();
#pragma unroll
    for (int r = 0; r < 32; r += 8) {
        int kk = k0 + ty + r;
        if (kk < K) dst[(size_t)kk * NPTS + i0 + tx] = t[tx][ty + r];
    }
}

// ======================= HMMA gather-conv ====================================
// R7 skeleton exactly (coalesced gather, depth-2 prefetch, 2 syncs/tap)
// + pipelined neighbor indices: idx block for tap t+2 rides in tap t's
//   cp.async group into smem slot (t+2)&3; read back with cheap LDS.
__device__ __forceinline__ void issue_tap(
    unsigned smem, const int* __restrict__ idxSlots, int tap, int K,
    const __half* feats, const __half* Wb, const int* nbrT,
    int row0, int tid)
{
    const int buf = tap & 1;
    const unsigned Ab = smem + (unsigned)buf*STG;
    const unsigned Bb = Ab + ABUF;
    const int* slot = idxSlots + (tap & 3) * 256;
    // A: 256 rows x 256B = 4096 chunks; 16 lanes cover one row (coalesced, as R7)
#pragma unroll
    for (int j = 0; j < 16; ++j) {
        int lin = tid + 256*j;
        int row = lin >> 4;
        int c   = lin & 15;
        int idx = nbrT ? slot[row] : (row0 + row);
        cp16(Ab + (unsigned)row*ROWB + (unsigned)c*16u,
             (const char*)(feats + (size_t)idx*CH) + c*16);
    }
    // B: 128 rows x 256B = 2048 chunks
    const char* wsrc = (const char*)(Wb + (size_t)tap*(CH*CH));
#pragma unroll
    for (int j = 0; j < 8; ++j) {
        int lin = tid + 256*j;
        int row = lin >> 4;
        int c   = lin & 15;
        cp16(Bb + (unsigned)row*ROWB + (unsigned)c*16u, wsrc + (size_t)row*256 + c*16);
    }
    // idx block for tap+2 -> slot (tap+2)&3 (1KB, 64 chunks)
    if (nbrT && tap + 2 < K && tid < 64) {
        unsigned dst = smem + 2u*STG + (unsigned)((tap + 2) & 3)*IDXSZ + (unsigned)tid*16u;
        cp16(dst, (const char*)(nbrT + (size_t)(tap + 2)*NPTS + row0) + tid*16);
    }
}

__global__ void __launch_bounds__(NT, 1)
tconv_kernel(const __half* __restrict__ feats,
             const __half* __restrict__ Wb,     // [K][128][128] fp16
             const int*    __restrict__ nbrT,   // [K][NPTS] or null
             const int K,
             const float*  __restrict__ gate,   // fp32 or null
             __half* __restrict__ out16,        // or null
             float*  __restrict__ out32)        // or null
{
    extern __shared__ char dsm[];
    const int tid  = threadIdx.x;
    const int lane = tid & 31;
    const int w    = tid >> 5;          // 0..7
    const int row0 = blockIdx.x * MROWS;
    const int m0   = (w >> 1) * 64;     // 4 m-groups of 64 rows
    const int n0   = (w & 1) * 64;      // 2 n-groups of 64 cols
    const unsigned smem = smem_to_u32(dsm);
    int* idxSlots = (int*)(dsm + 2*STG);

    // prologue: fill idx slots 0,1 synchronously, then issue taps 0,1
    if (nbrT) {
        idxSlots[tid]       = nbrT[row0 + tid];
        idxSlots[256 + tid] = (K > 1) ? nbrT[(size_t)NPTS + row0 + tid] : 0;
        __syncthreads();
    }
    issue_tap(smem, idxSlots, 0, K, feats, Wb, nbrT, row0, tid);
    CP_COMMIT();
    if (K > 1) {
        issue_tap(smem, idxSlots, 1, K, feats, Wb, nbrT, row0, tid);
        CP_COMMIT();
    }

    float acc[4][8][4];
#pragma unroll
    for (int i = 0; i < 4; ++i)
#pragma unroll
        for (int j = 0; j < 8; ++j)
#pragma unroll
            for (int e = 0; e < 4; ++e) acc[i][j][e] = 0.f;

    const unsigned lane_off = (unsigned)(lane & 15) * ROWB + (unsigned)(lane >> 4) * 16u;

    for (int k = 0; k < K; ++k) {
        const int buf = k & 1;
        if (k + 1 < K) { CP_WAIT(1); } else { CP_WAIT(0); }
        __syncthreads();   // tap k (and its idx slot for k+2) visible to all

        const unsigned Ab = smem + (unsigned)buf*STG;
        const unsigned Bb = Ab + ABUF;

#pragma unroll
        for (int ks = 0; ks < 8; ++ks) {
            unsigned a[4][4];
            unsigned abase = Ab + (unsigned)m0*ROWB + (unsigned)ks*32u + lane_off;
#pragma unroll
            for (int q = 0; q < 4; ++q) ldsm_x4(a[q], abase + (unsigned)q*16u*ROWB);
            unsigned bbase = Bb + (unsigned)ks*16u*ROWB + (unsigned)n0*2u + lane_off;
            unsigned b[4][4];
#pragma unroll
            for (int p = 0; p < 4; ++p) ldsm_x4_t(b[p], bbase + (unsigned)p*32u);
#pragma unroll
            for (int p = 0; p < 4; ++p) {
#pragma unroll
                for (int q = 0; q < 4; ++q) {
                    mma16816(acc[q][2*p],   a[q], b[p][0], b[p][1]);
                    mma16816(acc[q][2*p+1], a[q], b[p][2], b[p][3]);
                }
            }
        }

        __syncthreads();   // all warps done reading buf before refill

        if (k + 2 < K) {
            issue_tap(smem, idxSlots, k + 2, K, feats, Wb, nbrT, row0, tid);
            CP_COMMIT();
        }
    }

    // epilogue (optional fp32 gate fused)
#pragma unroll
    for (int msub = 0; msub < 4; ++msub) {
#pragma unroll
        for (int nb = 0; nb < 8; ++nb) {
#pragma unroll
            for (int ep = 0; ep < 2; ++ep) {
                int row = row0 + m0 + msub*16 + (lane >> 2) + ep*8;
                int col = n0 + nb*8 + (lane & 3)*2;
                float v0 = acc[msub][nb][ep*2];
                float v1 = acc[msub][nb][ep*2 + 1];
                size_t off = (size_t)row * CH + col;
                if (gate) {
                    float2 g = *reinterpret_cast<const float2*>(gate + off);
                    v0 *= g.x; v1 *= g.y;
                }
                if (out32) *reinterpret_cast<float2*>(out32 + off) = make_float2(v0, v1);
                if (out16) *reinterpret_cast<__half2*>(out16 + off) = __floats2half2_rn(v0, v1);
            }
        }
    }
}

// ======================= SIMT 1x1 GEMMs, both in one launch =================
#define TM 128
#define KC 32
#define SMEM_FLOATS (TM*CH + KC*CH + TM)
#define SMEM_BYTES  (SMEM_FLOATS * 4)
__global__ void __launch_bounds__(NT, 2)
sconv_av(const float* __restrict__ x,
         const float* __restrict__ Wa1, const float* __restrict__ Wv1,
         __half* __restrict__ Ah, float* __restrict__ V)
{
    extern __shared__ float smem[];
    float* Fs = smem;
    float* Ws = smem + TM*CH;
    const int tid = threadIdx.x;
    const bool isA = blockIdx.x < (NPTS/TM);
    const int row0 = (isA ? blockIdx.x : blockIdx.x - NPTS/TM) * TM;
    const float* Wt = isA ? Wa1 : Wv1;
    const int tcx = tid & 15, tcy = tid >> 4;
    float acc[8][8];
#pragma unroll
    for (int r = 0; r < 8; ++r)
#pragma unroll
        for (int c = 0; c < 8; ++c) acc[r][c] = 0.f;

#pragma unroll
    for (int j = 0; j < (TM*CH/4)/NT; ++j) {
        int lin = tid + j*NT;
        int r = lin >> 5, c4 = lin & 31;
        reinterpret_cast<float4*>(Fs + r*CH)[c4] =
            reinterpret_cast<const float4*>(x + (size_t)(row0 + r)*CH)[c4];
    }
#pragma unroll 1
    for (int cc = 0; cc < CH/KC; ++cc) {
        __syncthreads();
#pragma unroll
        for (int j = 0; j < 4; ++j) {
            int lin = tid + j*NT;
            reinterpret_cast<float4*>(Ws)[lin] =
                reinterpret_cast<const float4*>(Wt + cc*(KC*CH))[lin];
        }
        __syncthreads();
        const float* fp = Fs + (tcy*8)*CH + cc*KC;
        const float4* wrow = reinterpret_cast<const float4*>(Ws);
#pragma unroll 4
        for (int ci = 0; ci < KC; ++ci) {
            float f[8];
#pragma unroll
            for (int r = 0; r < 8; ++r) f[r] = fp[r*CH + ci];
            float4 w0 = wrow[ci*(CH/4) + tcx*2];
            float4 w1 = wrow[ci*(CH/4) + tcx*2 + 1];
            float wv[8] = {w0.x, w0.y, w0.z, w0.w, w1.x, w1.y, w1.z, w1.w};
#pragma unroll
            for (int r = 0; r < 8; ++r)
#pragma unroll
                for (int c = 0; c < 8; ++c)
                    acc[r][c] = fmaf(f[r], wv[c], acc[r][c]);
        }
    }
#pragma unroll
    for (int r = 0; r < 8; ++r) {
        size_t base = (size_t)(row0 + tcy*8 + r)*CH + tcx*8;
        if (isA) {
            __half2* hp = reinterpret_cast<__half2*>(Ah + base);
            hp[0] = __floats2half2_rn(acc[r][0], acc[r][1]);
            hp[1] = __floats2half2_rn(acc[r][2], acc[r][3]);
            hp[2] = __floats2half2_rn(acc[r][4], acc[r][5]);
            hp[3] = __floats2half2_rn(acc[r][6], acc[r][7]);
        } else {
            *reinterpret_cast<float4*>(V + base)     = make_float4(acc[r][0],acc[r][1],acc[r][2],acc[r][3]);
            *reinterpret_cast<float4*>(V + base + 4) = make_float4(acc[r][4],acc[r][5],acc[r][6],acc[r][7]);
        }
    }
}

// ======================= BN / elementwise =======================
__global__ void bn_partial_kernel(const float* __restrict__ y)
{
    int tid = threadIdx.x;
    int c = tid & (CH-1), half = tid >> 7;
    int rbase = blockIdx.x * 512 + half;
    float s = 0.f, s2 = 0.f;
#pragma unroll 8
    for (int j = 0; j < 256; ++j) {
        float v = y[(size_t)(rbase + 2*j)*CH + c];
        s += v; s2 = fmaf(v, v, s2);
    }
    g_part[blockIdx.x*256 + tid]          = s;
    g_part[64*256 + blockIdx.x*256 + tid] = s2;
}
__global__ void bn_finalize_kernel(const float* __restrict__ gamma, const float* __restrict__ beta)
{
    int c = threadIdx.x;
    float s = 0.f, s2 = 0.f;
    for (int b = 0; b < 64; ++b) {
        s  += g_part[b*256 + c] + g_part[b*256 + CH + c];
        s2 += g_part[64*256 + b*256 + c] + g_part[64*256 + b*256 + CH + c];
    }
    const float inv = 1.0f / (float)NPTS;
    float mu = s * inv;
    float var = s2 * inv - mu*mu;
    float sc = gamma[c] * rsqrtf(var + 1e-5f);
    g_scale[c] = sc;
    g_shift[c] = fmaf(-mu, sc, beta[c]);
}
__global__ void ew1_kernel(const float* __restrict__ y, const float* __restrict__ x)
{
    size_t i = (size_t)blockIdx.x * blockDim.x + threadIdx.x;
    float4 yv = reinterpret_cast<const float4*>(y)[i];
    float4 xv = reinterpret_cast<const float4*>(x)[i];
    int cg = (int)(i & 31);
    float4 sc = reinterpret_cast<const float4*>(g_scale)[cg];
    float4 sh = reinterpret_cast<const float4*>(g_shift)[cg];
    float4 r2;
    r2.x = fmaf(yv.x, sc.x, sh.x) + xv.x;
    r2.y = fmaf(yv.y, sc.y, sh.y) + xv.y;
    r2.z = fmaf(yv.z, sc.z, sh.z) + xv.z;
    r2.w = fmaf(yv.w, sc.w, sh.w) + xv.w;
    reinterpret_cast<float4*>(g_R)[i] = r2;
    reinterpret_cast<__half2*>(g_Th)[2*i]   = __floats2half2_rn(fmaxf(r2.x,0.f), fmaxf(r2.y,0.f));
    reinterpret_cast<__half2*>(g_Th)[2*i+1] = __floats2half2_rn(fmaxf(r2.z,0.f), fmaxf(r2.w,0.f));
}
__global__ void ew2_kernel(const float* __restrict__ y, float* __restrict__ out)
{
    size_t i = (size_t)blockIdx.x * blockDim.x + threadIdx.x;
    float4 yv = reinterpret_cast<const float4*>(y)[i];
    float4 rv = reinterpret_cast<const float4*>(g_R)[i];
    int cg = (int)(i & 31);
    float4 sc = reinterpret_cast<const float4*>(g_scale)[cg];
    float4 sh = reinterpret_cast<const float4*>(g_shift)[cg];
    float4 o;
    o.x = fmaxf(fmaf(yv.x, sc.x, sh.x) + rv.x, 0.f);
    o.y = fmaxf(fmaf(yv.y, sc.y, sh.y) + rv.y, 0.f);
    o.z = fmaxf(fmaf(yv.z, sc.z, sh.z) + rv.z, 0.f);
    o.w = fmaxf(fmaf(yv.w, sc.w, sh.w) + rv.w, 0.f);
    reinterpret_cast<float4*>(out)[i] = o;
}

// ======================= launch =======================
extern "C" void kernel_launch(void* const* d_in, const int* in_sizes, int n_in,
                              void* d_out, int out_size)
{
    const float* x      = (const float*)d_in[0];
    const float* Wa1    = (const float*)d_in[1];
    const float* Wv1    = (const float*)d_in[2];
    const float* W5     = (const float*)d_in[3];
    const float* W31    = (const float*)d_in[4];
    const float* W32    = (const float*)d_in[5];
    const float* gamma1 = (const float*)d_in[6];
    const float* beta1  = (const float*)d_in[7];
    const float* gamma2 = (const float*)d_in[8];
    const float* beta2  = (const float*)d_in[9];
    const int*   nbr5   = (const int*)d_in[10];
    const int*   nbr3a  = (const int*)d_in[11];
    const int*   nbr3b  = (const int*)d_in[12];
    float* out = (float*)d_out;

    float *pV, *pY;
    __half *pAh, *pGh, *pTh, *pW5b, *pW31b, *pW32b;
    int *pn5, *pn3a, *pn3b;
    cudaGetSymbolAddress((void**)&pV,  g_V);
    cudaGetSymbolAddress((void**)&pY,  g_Y);
    cudaGetSymbolAddress((void**)&pAh, g_Ah);
    cudaGetSymbolAddress((void**)&pGh, g_Gh);
    cudaGetSymbolAddress((void**)&pTh, g_Th);
    cudaGetSymbolAddress((void**)&pW5b, g_W5b);
    cudaGetSymbolAddress((void**)&pW31b, g_W31b);
    cudaGetSymbolAddress((void**)&pW32b, g_W32b);
    cudaGetSymbolAddress((void**)&pn5,  g_nT5);
    cudaGetSymbolAddress((void**)&pn3a, g_nT3a);
    cudaGetSymbolAddress((void**)&pn3b, g_nT3b);

    cudaFuncSetAttribute(sconv_av, cudaFuncAttributeMaxDynamicSharedMemorySize, SMEM_BYTES);
    cudaFuncSetAttribute(tconv_kernel, cudaFuncAttributeMaxDynamicSharedMemorySize, TCONV_SMEM);

    const int tgrid = NPTS / MROWS;       // 128
    const int ewgrid = (NPTS*CH/4) / 256;

    // 1: weight images   2: neighbor transposes
    wprep_all<<<179*64, 256>>>(W5, W31, W32, pW5b, pW31b, pW32b);
    ntr_all<<<dim3(6, NPTS/32), 256>>>(nbr5, nbr3a, nbr3b, pn5, pn3a, pn3b);
    // 3: a = fp16(x @ Wa1) AND v = fp32(x @ Wv1)
    sconv_av<<<2*(NPTS/TM), NT, SMEM_BYTES>>>(x, Wa1, Wv1, pAh, pV);
    // 4: Gh = fp16( conv5(a) * v )  -- gate fused; ncu captures this launch
    tconv_kernel<<<tgrid, NT, TCONV_SMEM>>>(pAh, pW5b, pn5, 125, pV, pGh, nullptr);
    // 5-8: conv3a -> BN1 -> ew1
    tconv_kernel<<<tgrid, NT, TCONV_SMEM>>>(pGh, pW31b, pn3a, 27, nullptr, nullptr, pY);
    bn_partial_kernel<<<64, 256>>>(pY);
    bn_finalize_kernel<<<1, 128>>>(gamma1, beta1);
    ew1_kernel<<<ewgrid, 256>>>(pY, x);
    // 9-12: conv3b -> BN2 -> ew2
    tconv_kernel<<<tgrid, NT, TCONV_SMEM>>>(pTh, pW32b, pn3b, 27, nullptr, nullptr, pY);
    bn_partial_kernel<<<64, 256>>>(pY);
    bn_finalize_kernel<<<1, 128>>>(gamma2, beta2);
    ew2_kernel<<<ewgrid, 256>>>(pY, out);
}

// round 14
// speedup vs baseline: 1.5112x; 1.0284x over previous
#include <cuda_runtime.h>
#include <cuda_fp16.h>

#define NPTS 32768
#define CH   128
#define NT   256

// ======================= baseline-PTX helpers =======================
__device__ __forceinline__ unsigned smem_to_u32(const void* p) {
    unsigned a;
    asm("{ .reg .u64 t; cvta.to.shared.u64 t, %1; cvt.u32.u64 %0, t; }" : "=r"(a) : "l"(p));
    return a;
}
__device__ __forceinline__ void cp16(unsigned dst, const void* src) {
    asm volatile("cp.async.cg.shared.global [%0], [%1], 16;" :: "r"(dst), "l"(src));
}
#define CP_COMMIT() asm volatile("cp.async.commit_group;" ::: "memory")
#define CP_WAIT(n)  asm volatile("cp.async.wait_group %0;" :: "n"(n) : "memory")

__device__ __forceinline__ void ldsm_x4(unsigned* r, unsigned addr) {
    asm volatile("ldmatrix.sync.aligned.m8n8.x4.shared.b16 {%0,%1,%2,%3}, [%4];"
        : "=r"(r[0]), "=r"(r[1]), "=r"(r[2]), "=r"(r[3]) : "r"(addr));
}
__device__ __forceinline__ void ldsm_x4_t(unsigned* r, unsigned addr) {
    asm volatile("ldmatrix.sync.aligned.m8n8.x4.trans.shared.b16 {%0,%1,%2,%3}, [%4];"
        : "=r"(r[0]), "=r"(r[1]), "=r"(r[2]), "=r"(r[3]) : "r"(addr));
}
__device__ __forceinline__ void mma16816(float* c, const unsigned* a, unsigned b0, unsigned b1) {
    asm volatile("mma.sync.aligned.m16n8k16.row.col.f32.f16.f16.f32 "
        "{%0,%1,%2,%3}, {%4,%5,%6,%7}, {%8,%9}, {%0,%1,%2,%3};"
        : "+f"(c[0]), "+f"(c[1]), "+f"(c[2]), "+f"(c[3])
        : "r"(a[0]), "r"(a[1]), "r"(a[2]), "r"(a[3]), "r"(b0), "r"(b1));
}

// ======================= tconv sizes (full-tap stages, M=256, 8 warps) =====
#define MROWS  256
#define ROWB   272                     // padded row stride (16B-aligned, ldsm-safe)
#define ABUF   (MROWS*ROWB)            // 69632
#define BBUF   (128*ROWB)              // 34816
#define STG    (ABUF + BBUF)           // 104448
#define IDXSZ  1024                    // 256 ints per slot
#define TCONV_SMEM (2*STG + 4*IDXSZ)   // 212992 (1 CTA/SM)

// ======================= scratch =======================
__device__ __align__(16) float  g_V [NPTS*CH];
__device__ __align__(16) float  g_Y [NPTS*CH];
__device__ __align__(16) float  g_R [NPTS*CH];
__device__ __align__(16) __half g_Ah[NPTS*CH];
__device__ __align__(16) __half g_Gh[NPTS*CH];
__device__ __align__(16) __half g_Th[NPTS*CH];
__device__ __align__(16) __half g_W5b [125*CH*CH];   // fp16 [k][ci][co]
__device__ __align__(16) __half g_W31b[27*CH*CH];
__device__ __align__(16) __half g_W32b[27*CH*CH];
__device__ int g_nT5 [125*NPTS];
__device__ int g_nT3a[27*NPTS];
__device__ int g_nT3b[27*NPTS];
__device__ __align__(16) float g_part[2*128*CH];     // per-CTA BN partials (s | s2)
__device__ __align__(16) float g_scale[CH];
__device__ __align__(16) float g_shift[CH];

// ======================= prep kernels (fused) =======================
__global__ void wprep_all(const float* __restrict__ W5, const float* __restrict__ W31,
                          const float* __restrict__ W32,
                          __half* __restrict__ o5, __half* __restrict__ o31,
                          __half* __restrict__ o32)
{
    int b = blockIdx.x;                 // 179*64 blocks
    const float* W; __half* O; int kb;
    if (b < 125*64)      { W = W5;  O = o5;  kb = b; }
    else if (b < 152*64) { W = W31; O = o31; kb = b - 125*64; }
    else                 { W = W32; O = o32; kb = b - 152*64; }
    int e = kb * 256 + threadIdx.x;
    O[e] = __float2half_rn(W[e]);
}

__global__ void ntr_all(const int* __restrict__ nbr5, const int* __restrict__ nbr3a,
                        const int* __restrict__ nbr3b,
                        int* __restrict__ n5, int* __restrict__ n3a, int* __restrict__ n3b)
{
    __shared__ int t[32][33];
    int bx = blockIdx.x;
    const int* src; int* dst; int K, k0;
    if (bx < 4)       { src = nbr5;  dst = n5;  K = 125; k0 = bx*32; }
    else if (bx == 4) { src = nbr3a; dst = n3a; K = 27;  k0 = 0; }
    else              { src = nbr3b; dst = n3b; K = 27;  k0 = 0; }
    int i0 = blockIdx.y * 32;
    int tx = threadIdx.x & 31, ty = threadIdx.x >> 5;
#pragma unroll
    for (int r = 0; r < 32; r += 8) {
        int kk = k0 + tx;
        t[ty + r][tx] = (kk < K) ? src[(size_t)(i0 + ty + r) * K + kk] : 0;
    }
    __syncthreads();
#pragma unroll
    for (int r = 0; r < 32; r += 8) {
        int kk = k0 + ty + r;
        if (kk < K) dst[(size_t)kk * NPTS + i0 + tx] = t[tx][ty + r];
    }
}

// ======================= HMMA gather-conv ====================================
// R13 skeleton (coalesced gather, depth-2 prefetch, 2 syncs/tap, smem idx pipe)
// + fused deterministic BN partial reduction in the epilogue (bnPart != null).
__device__ __forceinline__ void issue_tap(
    unsigned smem, const int* __restrict__ idxSlots, int tap, int K,
    const __half* feats, const __half* Wb, const int* nbrT,
    int row0, int tid)
{
    const int buf = tap & 1;
    const unsigned Ab = smem + (unsigned)buf*STG;
    const unsigned Bb = Ab + ABUF;
    const int* slot = idxSlots + (tap & 3) * 256;
    // A: 256 rows x 256B = 4096 chunks; 16 lanes cover one row (coalesced)
#pragma unroll
    for (int j = 0; j < 16; ++j) {
        int lin = tid + 256*j;
        int row = lin >> 4;
        int c   = lin & 15;
        int idx = nbrT ? slot[row] : (row0 + row);
        cp16(Ab + (unsigned)row*ROWB + (unsigned)c*16u,
             (const char*)(feats + (size_t)idx*CH) + c*16);
    }
    // B: 128 rows x 256B = 2048 chunks
    const char* wsrc = (const char*)(Wb + (size_t)tap*(CH*CH));
#pragma unroll
    for (int j = 0; j < 8; ++j) {
        int lin = tid + 256*j;
        int row = lin >> 4;
        int c   = lin & 15;
        cp16(Bb + (unsigned)row*ROWB + (unsigned)c*16u, wsrc + (size_t)row*256 + c*16);
    }
    // idx block for tap+2 -> slot (tap+2)&3 (1KB, 64 chunks)
    if (nbrT && tap + 2 < K && tid < 64) {
        unsigned dst = smem + 2u*STG + (unsigned)((tap + 2) & 3)*IDXSZ + (unsigned)tid*16u;
        cp16(dst, (const char*)(nbrT + (size_t)(tap + 2)*NPTS + row0) + tid*16);
    }
}

__global__ void __launch_bounds__(NT, 1)
tconv_kernel(const __half* __restrict__ feats,
             const __half* __restrict__ Wb,     // [K][128][128] fp16
             const int*    __restrict__ nbrT,   // [K][NPTS] or null
             const int K,
             const float*  __restrict__ gate,   // fp32 or null
             __half* __restrict__ out16,        // or null
             float*  __restrict__ out32,        // or null
             float*  __restrict__ bnPart)       // per-CTA BN partials or null
{
    extern __shared__ char dsm[];
    const int tid  = threadIdx.x;
    const int lane = tid & 31;
    const int w    = tid >> 5;          // 0..7
    const int row0 = blockIdx.x * MROWS;
    const int m0   = (w >> 1) * 64;     // 4 m-groups of 64 rows
    const int n0   = (w & 1) * 64;      // 2 n-groups of 64 cols
    const unsigned smem = smem_to_u32(dsm);
    int* idxSlots = (int*)(dsm + 2*STG);

    // prologue: fill idx slots 0,1 synchronously, then issue taps 0,1
    if (nbrT) {
        idxSlots[tid]       = nbrT[row0 + tid];
        idxSlots[256 + tid] = (K > 1) ? nbrT[(size_t)NPTS + row0 + tid] : 0;
        __syncthreads();
    }
    issue_tap(smem, idxSlots, 0, K, feats, Wb, nbrT, row0, tid);
    CP_COMMIT();
    if (K > 1) {
        issue_tap(smem, idxSlots, 1, K, feats, Wb, nbrT, row0, tid);
        CP_COMMIT();
    }

    float acc[4][8][4];
#pragma unroll
    for (int i = 0; i < 4; ++i)
#pragma unroll
        for (int j = 0; j < 8; ++j)
#pragma unroll
            for (int e = 0; e < 4; ++e) acc[i][j][e] = 0.f;

    const unsigned lane_off = (unsigned)(lane & 15) * ROWB + (unsigned)(lane >> 4) * 16u;

    for (int k = 0; k < K; ++k) {
        const int buf = k & 1;
        if (k + 1 < K) { CP_WAIT(1); } else { CP_WAIT(0); }
        __syncthreads();   // tap k (and its idx slot for k+2) visible to all

        const unsigned Ab = smem + (unsigned)buf*STG;
        const unsigned Bb = Ab + ABUF;

#pragma unroll
        for (int ks = 0; ks < 8; ++ks) {
            unsigned a[4][4];
            unsigned abase = Ab + (unsigned)m0*ROWB + (unsigned)ks*32u + lane_off;
#pragma unroll
            for (int q = 0; q < 4; ++q) ldsm_x4(a[q], abase + (unsigned)q*16u*ROWB);
            unsigned bbase = Bb + (unsigned)ks*16u*ROWB + (unsigned)n0*2u + lane_off;
            unsigned b[4][4];
#pragma unroll
            for (int p = 0; p < 4; ++p) ldsm_x4_t(b[p], bbase + (unsigned)p*32u);
#pragma unroll
            for (int p = 0; p < 4; ++p) {
#pragma unroll
                for (int q = 0; q < 4; ++q) {
                    mma16816(acc[q][2*p],   a[q], b[p][0], b[p][1]);
                    mma16816(acc[q][2*p+1], a[q], b[p][2], b[p][3]);
                }
            }
        }

        __syncthreads();   // all warps done reading buf before refill

        if (k + 2 < K) {
            issue_tap(smem, idxSlots, k + 2, K, feats, Wb, nbrT, row0, tid);
            CP_COMMIT();
        }
    }

    // ===== epilogue: store (+optional gate) and optional fused BN partials ====
    // After the loop every thread has passed the final sync2 -> smem is dead;
    // reuse dsm[0..4KB) as per-warp reduction scratch (disjoint slices, no race).
    float* red = (float*)dsm;   // [warp][128]: cols 0..63 = s, 64..127 = s2

#pragma unroll
    for (int nb = 0; nb < 8; ++nb) {
        float s0 = 0.f, s1 = 0.f, q0 = 0.f, q1 = 0.f;
#pragma unroll
        for (int msub = 0; msub < 4; ++msub) {
#pragma unroll
            for (int ep = 0; ep < 2; ++ep) {
                int row = row0 + m0 + msub*16 + (lane >> 2) + ep*8;
                int col = n0 + nb*8 + (lane & 3)*2;
                float v0 = acc[msub][nb][ep*2];
                float v1 = acc[msub][nb][ep*2 + 1];
                size_t off = (size_t)row * CH + col;
                if (gate) {
                    float2 g = *reinterpret_cast<const float2*>(gate + off);
                    v0 *= g.x; v1 *= g.y;
                }
                if (out32) *reinterpret_cast<float2*>(out32 + off) = make_float2(v0, v1);
                if (out16) *reinterpret_cast<__half2*>(out16 + off) = __floats2half2_rn(v0, v1);
                s0 += v0; s1 += v1;
                q0 = fmaf(v0, v0, q0); q1 = fmaf(v1, v1, q1);
            }
        }
        if (bnPart) {
            // reduce over the 8 lanes sharing (lane & 3) — offsets 16,8,4
#pragma unroll
            for (int off = 16; off >= 4; off >>= 1) {
                s0 += __shfl_down_sync(0xffffffffu, s0, off);
                s1 += __shfl_down_sync(0xffffffffu, s1, off);
                q0 += __shfl_down_sync(0xffffffffu, q0, off);
                q1 += __shfl_down_sync(0xffffffffu, q1, off);
            }
            if (lane < 4) {
                int lc = nb*8 + lane*2;          // local col within warp's 64
                red[w*128 + lc]        = s0;
                red[w*128 + lc + 1]    = s1;
                red[w*128 + 64 + lc]       = q0;
                red[w*128 + 64 + lc + 1]   = q1;
            }
        }
    }
    if (bnPart) {
        __syncthreads();
        if (tid < CH) {
            int half = tid >> 6;       // which n-half owns this column
            int lc   = tid & 63;
            float s = 0.f, q = 0.f;
#pragma unroll
            for (int j = 0; j < 4; ++j) {        // 4 m-warps of that n-half
                s += red[(2*j + half)*128 + lc];
                q += red[(2*j + half)*128 + 64 + lc];
            }
            bnPart[blockIdx.x*CH + tid]            = s;
            bnPart[128*CH + blockIdx.x*CH + tid]   = q;
        }
    }
}

// ======================= SIMT 1x1 GEMMs, both in one launch =================
#define TM 128
#define KC 32
#define SMEM_FLOATS (TM*CH + KC*CH + TM)
#define SMEM_BYTES  (SMEM_FLOATS * 4)
__global__ void __launch_bounds__(NT, 2)
sconv_av(const float* __restrict__ x,
         const float* __restrict__ Wa1, const float* __restrict__ Wv1,
         __half* __restrict__ Ah, float* __restrict__ V)
{
    extern __shared__ float smem[];
    float* Fs = smem;
    float* Ws = smem + TM*CH;
    const int tid = threadIdx.x;
    const bool isA = blockIdx.x < (NPTS/TM);
    const int row0 = (isA ? blockIdx.x : blockIdx.x - NPTS/TM) * TM;
    const float* Wt = isA ? Wa1 : Wv1;
    const int tcx = tid & 15, tcy = tid >> 4;
    float acc[8][8];
#pragma unroll
    for (int r = 0; r < 8; ++r)
#pragma unroll
        for (int c = 0; c < 8; ++c) acc[r][c] = 0.f;

#pragma unroll
    for (int j = 0; j < (TM*CH/4)/NT; ++j) {
        int lin = tid + j*NT;
        int r = lin >> 5, c4 = lin & 31;
        reinterpret_cast<float4*>(Fs + r*CH)[c4] =
            reinterpret_cast<const float4*>(x + (size_t)(row0 + r)*CH)[c4];
    }
#pragma unroll 1
    for (int cc = 0; cc < CH/KC; ++cc) {
        __syncthreads();
#pragma unroll
        for (int j = 0; j < 4; ++j) {
            int lin = tid + j*NT;
            reinterpret_cast<float4*>(Ws)[lin] =
                reinterpret_cast<const float4*>(Wt + cc*(KC*CH))[lin];
        }
        __syncthreads();
        const float* fp = Fs + (tcy*8)*CH + cc*KC;
        const float4* wrow = reinterpret_cast<const float4*>(Ws);
#pragma unroll 4
        for (int ci = 0; ci < KC; ++ci) {
            float f[8];
#pragma unroll
            for (int r = 0; r < 8; ++r) f[r] = fp[r*CH + ci];
            float4 w0 = wrow[ci*(CH/4) + tcx*2];
            float4 w1 = wrow[ci*(CH/4) + tcx*2 + 1];
            float wv[8] = {w0.x, w0.y, w0.z, w0.w, w1.x, w1.y, w1.z, w1.w};
#pragma unroll
            for (int r = 0; r < 8; ++r)
#pragma unroll
                for (int c = 0; c < 8; ++c)
                    acc[r][c] = fmaf(f[r], wv[c], acc[r][c]);
        }
    }
#pragma unroll
    for (int r = 0; r < 8; ++r) {
        size_t base = (size_t)(row0 + tcy*8 + r)*CH + tcx*8;
        if (isA) {
            __half2* hp = reinterpret_cast<__half2*>(Ah + base);
            hp[0] = __floats2half2_rn(acc[r][0], acc[r][1]);
            hp[1] = __floats2half2_rn(acc[r][2], acc[r][3]);
            hp[2] = __floats2half2_rn(acc[r][4], acc[r][5]);
            hp[3] = __floats2half2_rn(acc[r][6], acc[r][7]);
        } else {
            *reinterpret_cast<float4*>(V + base)     = make_float4(acc[r][0],acc[r][1],acc[r][2],acc[r][3]);
            *reinterpret_cast<float4*>(V + base + 4) = make_float4(acc[r][4],acc[r][5],acc[r][6],acc[r][7]);
        }
    }
}

// ======================= BN / elementwise =======================
__global__ void bn_finalize_kernel(const float* __restrict__ gamma, const float* __restrict__ beta)
{
    int c = threadIdx.x;  // 128
    float s = 0.f, s2 = 0.f;
    for (int b = 0; b < 128; ++b) {
        s  += g_part[b*CH + c];
        s2 += g_part[128*CH + b*CH + c];
    }
    const float inv = 1.0f / (float)NPTS;
    float mu = s * inv;
    float var = s2 * inv - mu*mu;
    float sc = gamma[c] * rsqrtf(var + 1e-5f);
    g_scale[c] = sc;
    g_shift[c] = fmaf(-mu, sc, beta[c]);
}
__global__ void ew1_kernel(const float* __restrict__ y, const float* __restrict__ x)
{
    size_t i = (size_t)blockIdx.x * blockDim.x + threadIdx.x;
    float4 yv = reinterpret_cast<const float4*>(y)[i];
    float4 xv = reinterpret_cast<const float4*>(x)[i];
    int cg = (int)(i & 31);
    float4 sc = reinterpret_cast<const float4*>(g_scale)[cg];
    float4 sh = reinterpret_cast<const float4*>(g_shift)[cg];
    float4 r2;
    r2.x = fmaf(yv.x, sc.x, sh.x) + xv.x;
    r2.y = fmaf(yv.y, sc.y, sh.y) + xv.y;
    r2.z = fmaf(yv.z, sc.z, sh.z) + xv.z;
    r2.w = fmaf(yv.w, sc.w, sh.w) + xv.w;
    reinterpret_cast<float4*>(g_R)[i] = r2;
    reinterpret_cast<__half2*>(g_Th)[2*i]   = __floats2half2_rn(fmaxf(r2.x,0.f), fmaxf(r2.y,0.f));
    reinterpret_cast<__half2*>(g_Th)[2*i+1] = __floats2half2_rn(fmaxf(r2.z,0.f), fmaxf(r2.w,0.f));
}
__global__ void ew2_kernel(const float* __restrict__ y, float* __restrict__ out)
{
    size_t i = (size_t)blockIdx.x * blockDim.x + threadIdx.x;
    float4 yv = reinterpret_cast<const float4*>(y)[i];
    float4 rv = reinterpret_cast<const float4*>(g_R)[i];
    int cg = (int)(i & 31);
    float4 sc = reinterpret_cast<const float4*>(g_scale)[cg];
    float4 sh = reinterpret_cast<const float4*>(g_shift)[cg];
    float4 o;
    o.x = fmaxf(fmaf(yv.x, sc.x, sh.x) + rv.x, 0.f);
    o.y = fmaxf(fmaf(yv.y, sc.y, sh.y) + rv.y, 0.f);
    o.z = fmaxf(fmaf(yv.z, sc.z, sh.z) + rv.z, 0.f);
    o.w = fmaxf(fmaf(yv.w, sc.w, sh.w) + rv.w, 0.f);
    reinterpret_cast<float4*>(out)[i] = o;
}

// ======================= launch =======================
extern "C" void kernel_launch(void* const* d_in, const int* in_sizes, int n_in,
                              void* d_out, int out_size)
{
    const float* x      = (const float*)d_in[0];
    const float* Wa1    = (const float*)d_in[1];
    const float* Wv1    = (const float*)d_in[2];
    const float* W5     = (const float*)d_in[3];
    const float* W31    = (const float*)d_in[4];
    const float* W32    = (const float*)d_in[5];
    const float* gamma1 = (const float*)d_in[6];
    const float* beta1  = (const float*)d_in[7];
    const float* gamma2 = (const float*)d_in[8];
    const float* beta2  = (const float*)d_in[9];
    const int*   nbr5   = (const int*)d_in[10];
    const int*   nbr3a  = (const int*)d_in[11];
    const int*   nbr3b  = (const int*)d_in[12];
    float* out = (float*)d_out;

    float *pV, *pY, *pPart;
    __half *pAh, *pGh, *pTh, *pW5b, *pW31b, *pW32b;
    int *pn5, *pn3a, *pn3b;
    cudaGetSymbolAddress((void**)&pV,  g_V);
    cudaGetSymbolAddress((void**)&pY,  g_Y);
    cudaGetSymbolAddress((void**)&pPart, g_part);
    cudaGetSymbolAddress((void**)&pAh, g_Ah);
    cudaGetSymbolAddress((void**)&pGh, g_Gh);
    cudaGetSymbolAddress((void**)&pTh, g_Th);
    cudaGetSymbolAddress((void**)&pW5b, g_W5b);
    cudaGetSymbolAddress((void**)&pW31b, g_W31b);
    cudaGetSymbolAddress((void**)&pW32b, g_W32b);
    cudaGetSymbolAddress((void**)&pn5,  g_nT5);
    cudaGetSymbolAddress((void**)&pn3a, g_nT3a);
    cudaGetSymbolAddress((void**)&pn3b, g_nT3b);

    cudaFuncSetAttribute(sconv_av, cudaFuncAttributeMaxDynamicSharedMemorySize, SMEM_BYTES);
    cudaFuncSetAttribute(tconv_kernel, cudaFuncAttributeMaxDynamicSharedMemorySize, TCONV_SMEM);

    const int tgrid = NPTS / MROWS;       // 128
    const int ewgrid = (NPTS*CH/4) / 256;

    // 1: weight images   2: neighbor transposes
    wprep_all<<<179*64, 256>>>(W5, W31, W32, pW5b, pW31b, pW32b);
    ntr_all<<<dim3(6, NPTS/32), 256>>>(nbr5, nbr3a, nbr3b, pn5, pn3a, pn3b);
    // 3: a = fp16(x @ Wa1) AND v = fp32(x @ Wv1)
    sconv_av<<<2*(NPTS/TM), NT, SMEM_BYTES>>>(x, Wa1, Wv1, pAh, pV);
    // 4: Gh = fp16( conv5(a) * v )  -- gate fused; ncu captures this launch
    tconv_kernel<<<tgrid, NT, TCONV_SMEM>>>(pAh, pW5b, pn5, 125, pV, pGh, nullptr, nullptr);
    // 5-7: conv3a (BN1 partials fused) -> BN1 finalize -> ew1
    tconv_kernel<<<tgrid, NT, TCONV_SMEM>>>(pGh, pW31b, pn3a, 27, nullptr, nullptr, pY, pPart);
    bn_finalize_kernel<<<1, 128>>>(gamma1, beta1);
    ew1_kernel<<<ewgrid, 256>>>(pY, x);
    // 8-10: conv3b (BN2 partials fused) -> BN2 finalize -> ew2
    tconv_kernel<<<tgrid, NT, TCONV_SMEM>>>(pTh, pW32b, pn3b, 27, nullptr, nullptr, pY, pPart);
    bn_finalize_kernel<<<1, 128>>>(gamma2, beta2);
    ew2_kernel<<<ewgrid, 256>>>(pY, out);
}

// round 15
// speedup vs baseline: 1.5993x; 1.0583x over previous
#include <cuda_runtime.h>
#include <cuda_fp16.h>

#define NPTS 32768
#define CH   128
#define NT   256

// ======================= baseline-PTX helpers =======================
__device__ __forceinline__ unsigned smem_to_u32(const void* p) {
    unsigned a;
    asm("{ .reg .u64 t; cvta.to.shared.u64 t, %1; cvt.u32.u64 %0, t; }" : "=r"(a) : "l"(p));
    return a;
}
__device__ __forceinline__ void cp16(unsigned dst, const void* src) {
    asm volatile("cp.async.cg.shared.global [%0], [%1], 16;" :: "r"(dst), "l"(src));
}
#define CP_COMMIT() asm volatile("cp.async.commit_group;" ::: "memory")
#define CP_WAIT(n)  asm volatile("cp.async.wait_group %0;" :: "n"(n) : "memory")

__device__ __forceinline__ void ldsm_x4(unsigned* r, unsigned addr) {
    asm volatile("ldmatrix.sync.aligned.m8n8.x4.shared.b16 {%0,%1,%2,%3}, [%4];"
        : "=r"(r[0]), "=r"(r[1]), "=r"(r[2]), "=r"(r[3]) : "r"(addr));
}
__device__ __forceinline__ void ldsm_x4_t(unsigned* r, unsigned addr) {
    asm volatile("ldmatrix.sync.aligned.m8n8.x4.trans.shared.b16 {%0,%1,%2,%3}, [%4];"
        : "=r"(r[0]), "=r"(r[1]), "=r"(r[2]), "=r"(r[3]) : "r"(addr));
}
__device__ __forceinline__ void mma16816(float* c, const unsigned* a, unsigned b0, unsigned b1) {
    asm volatile("mma.sync.aligned.m16n8k16.row.col.f32.f16.f16.f32 "
        "{%0,%1,%2,%3}, {%4,%5,%6,%7}, {%8,%9}, {%0,%1,%2,%3};"
        : "+f"(c[0]), "+f"(c[1]), "+f"(c[2]), "+f"(c[3])
        : "r"(a[0]), "r"(a[1]), "r"(a[2]), "r"(a[3]), "r"(b0), "r"(b1));
}

// ======================= tconv sizes (full-tap stages, M=256, 8 warps) =====
#define MROWS  256
#define ROWB   272                     // padded row stride (16B-aligned, ldsm-safe)
#define ABUF   (MROWS*ROWB)            // 69632
#define BBUF   (128*ROWB)              // 34816
#define STG    (ABUF + BBUF)           // 104448
#define IDXSZ  1024                    // 256 ints per slot
#define TCONV_SMEM (2*STG + 4*IDXSZ)   // 212992 (1 CTA/SM)

// ======================= scratch =======================
__device__ __align__(16) float  g_V [NPTS*CH];
__device__ __align__(16) float  g_Y [NPTS*CH];
__device__ __align__(16) float  g_R [NPTS*CH];
__device__ __align__(16) __half g_Xh[NPTS*CH];
__device__ __align__(16) __half g_Ah[NPTS*CH];
__device__ __align__(16) __half g_Gh[NPTS*CH];
__device__ __align__(16) __half g_Th[NPTS*CH];
__device__ __align__(16) __half g_W5b [125*CH*CH];   // fp16 [k][ci][co]
__device__ __align__(16) __half g_W31b[27*CH*CH];
__device__ __align__(16) __half g_W32b[27*CH*CH];
__device__ __align__(16) __half g_Wa1b[CH*CH];
__device__ __align__(16) __half g_Wv1b[CH*CH];
__device__ int g_nT5 [125*NPTS];
__device__ int g_nT3a[27*NPTS];
__device__ int g_nT3b[27*NPTS];
__device__ __align__(16) float g_part[2*128*CH];     // per-CTA BN partials (s | s2)
__device__ __align__(16) float g_scale[CH];
__device__ __align__(16) float g_shift[CH];

// ======================= prep kernels (fused) =======================
// All five weight tensors -> fp16 images in ONE launch (181*64 blocks).
__global__ void wprep_all(const float* __restrict__ W5, const float* __restrict__ W31,
                          const float* __restrict__ W32,
                          const float* __restrict__ Wa1, const float* __restrict__ Wv1,
                          __half* __restrict__ o5, __half* __restrict__ o31,
                          __half* __restrict__ o32,
                          __half* __restrict__ oa, __half* __restrict__ ov)
{
    int b = blockIdx.x;
    const float* W; __half* O; int kb;
    if (b < 125*64)      { W = W5;  O = o5;  kb = b; }
    else if (b < 152*64) { W = W31; O = o31; kb = b - 125*64; }
    else if (b < 179*64) { W = W32; O = o32; kb = b - 152*64; }
    else if (b < 180*64) { W = Wa1; O = oa;  kb = b - 179*64; }
    else                 { W = Wv1; O = ov;  kb = b - 180*64; }
    int e = kb * 256 + threadIdx.x;
    O[e] = __float2half_rn(W[e]);
}

__global__ void ntr_all(const int* __restrict__ nbr5, const int* __restrict__ nbr3a,
                        const int* __restrict__ nbr3b,
                        int* __restrict__ n5, int* __restrict__ n3a, int* __restrict__ n3b)
{
    __shared__ int t[32][33];
    int bx = blockIdx.x;
    const int* src; int* dst; int K, k0;
    if (bx < 4)       { src = nbr5;  dst = n5;  K = 125; k0 = bx*32; }
    else if (bx == 4) { src = nbr3a; dst = n3a; K = 27;  k0 = 0; }
    else              { src = nbr3b; dst = n3b; K = 27;  k0 = 0; }
    int i0 = blockIdx.y * 32;
    int tx = threadIdx.x & 31, ty = threadIdx.x >> 5;
#pragma unroll
    for (int r = 0; r < 32; r += 8) {
        int kk = k0 + tx;
        t[ty + r][tx] = (kk < K) ? src[(size_t)(i0 + ty + r) * K + kk] : 0;
    }
    __syncthreads();
#pragma unroll
    for (int r = 0; r < 32; r += 8) {
        int kk = k0 + ty + r;
        if (kk < K) dst[(size_t)kk * NPTS + i0 + tx] = t[tx][ty + r];
    }
}

__global__ void cvt_kernel(const float* __restrict__ in, __half* __restrict__ out)
{
    int i = blockIdx.x * 256 + threadIdx.x;       // float4 units
    float4 v = reinterpret_cast<const float4*>(in)[i];
    reinterpret_cast<__half2*>(out)[2*i]   = __floats2half2_rn(v.x, v.y);
    reinterpret_cast<__half2*>(out)[2*i+1] = __floats2half2_rn(v.z, v.w);
}

// ======================= HMMA gather-conv ====================================
// R13 skeleton (coalesced gather, depth-2 prefetch, 2 syncs/tap, smem idx pipe)
// + fused deterministic BN partial reduction (bnPart != null).
__device__ __forceinline__ void issue_tap(
    unsigned smem, const int* __restrict__ idxSlots, int tap, int K,
    const __half* feats, const __half* Wb, const int* nbrT,
    int row0, int tid)
{
    const int buf = tap & 1;
    const unsigned Ab = smem + (unsigned)buf*STG;
    const unsigned Bb = Ab + ABUF;
    const int* slot = idxSlots + (tap & 3) * 256;
    // A: 256 rows x 256B = 4096 chunks; 16 lanes cover one row (coalesced)
#pragma unroll
    for (int j = 0; j < 16; ++j) {
        int lin = tid + 256*j;
        int row = lin >> 4;
        int c   = lin & 15;
        int idx = nbrT ? slot[row] : (row0 + row);
        cp16(Ab + (unsigned)row*ROWB + (unsigned)c*16u,
             (const char*)(feats + (size_t)idx*CH) + c*16);
    }
    // B: 128 rows x 256B = 2048 chunks
    const char* wsrc = (const char*)(Wb + (size_t)tap*(CH*CH));
#pragma unroll
    for (int j = 0; j < 8; ++j) {
        int lin = tid + 256*j;
        int row = lin >> 4;
        int c   = lin & 15;
        cp16(Bb + (unsigned)row*ROWB + (unsigned)c*16u, wsrc + (size_t)row*256 + c*16);
    }
    // idx block for tap+2 -> slot (tap+2)&3 (1KB, 64 chunks)
    if (nbrT && tap + 2 < K && tid < 64) {
        unsigned dst = smem + 2u*STG + (unsigned)((tap + 2) & 3)*IDXSZ + (unsigned)tid*16u;
        cp16(dst, (const char*)(nbrT + (size_t)(tap + 2)*NPTS + row0) + tid*16);
    }
}

__global__ void __launch_bounds__(NT, 1)
tconv_kernel(const __half* __restrict__ feats,
             const __half* __restrict__ Wb,     // [K][128][128] fp16
             const int*    __restrict__ nbrT,   // [K][NPTS] or null
             const int K,
             const float*  __restrict__ gate,   // fp32 or null
             __half* __restrict__ out16,        // or null
             float*  __restrict__ out32,        // or null
             float*  __restrict__ bnPart)       // per-CTA BN partials or null
{
    extern __shared__ char dsm[];
    const int tid  = threadIdx.x;
    const int lane = tid & 31;
    const int w    = tid >> 5;          // 0..7
    const int row0 = blockIdx.x * MROWS;
    const int m0   = (w >> 1) * 64;     // 4 m-groups of 64 rows
    const int n0   = (w & 1) * 64;      // 2 n-groups of 64 cols
    const unsigned smem = smem_to_u32(dsm);
    int* idxSlots = (int*)(dsm + 2*STG);

    // prologue: fill idx slots 0,1 synchronously, then issue taps 0,1
    if (nbrT) {
        idxSlots[tid]       = nbrT[row0 + tid];
        idxSlots[256 + tid] = (K > 1) ? nbrT[(size_t)NPTS + row0 + tid] : 0;
        __syncthreads();
    }
    issue_tap(smem, idxSlots, 0, K, feats, Wb, nbrT, row0, tid);
    CP_COMMIT();
    if (K > 1) {
        issue_tap(smem, idxSlots, 1, K, feats, Wb, nbrT, row0, tid);
        CP_COMMIT();
    }

    float acc[4][8][4];
#pragma unroll
    for (int i = 0; i < 4; ++i)
#pragma unroll
        for (int j = 0; j < 8; ++j)
#pragma unroll
            for (int e = 0; e < 4; ++e) acc[i][j][e] = 0.f;

    const unsigned lane_off = (unsigned)(lane & 15) * ROWB + (unsigned)(lane >> 4) * 16u;

    for (int k = 0; k < K; ++k) {
        const int buf = k & 1;
        if (k + 1 < K) { CP_WAIT(1); } else { CP_WAIT(0); }
        __syncthreads();   // tap k (and its idx slot for k+2) visible to all

        const unsigned Ab = smem + (unsigned)buf*STG;
        const unsigned Bb = Ab + ABUF;

#pragma unroll
        for (int ks = 0; ks < 8; ++ks) {
            unsigned a[4][4];
            unsigned abase = Ab + (unsigned)m0*ROWB + (unsigned)ks*32u + lane_off;
#pragma unroll
            for (int q = 0; q < 4; ++q) ldsm_x4(a[q], abase + (unsigned)q*16u*ROWB);
            unsigned bbase = Bb + (unsigned)ks*16u*ROWB + (unsigned)n0*2u + lane_off;
            unsigned b[4][4];
#pragma unroll
            for (int p = 0; p < 4; ++p) ldsm_x4_t(b[p], bbase + (unsigned)p*32u);
#pragma unroll
            for (int p = 0; p < 4; ++p) {
#pragma unroll
                for (int q = 0; q < 4; ++q) {
                    mma16816(acc[q][2*p],   a[q], b[p][0], b[p][1]);
                    mma16816(acc[q][2*p+1], a[q], b[p][2], b[p][3]);
                }
            }
        }

        __syncthreads();   // all warps done reading buf before refill

        if (k + 2 < K) {
            issue_tap(smem, idxSlots, k + 2, K, feats, Wb, nbrT, row0, tid);
            CP_COMMIT();
        }
    }

    // ===== epilogue: store (+optional gate) and optional fused BN partials ====
    float* red = (float*)dsm;   // [warp][128]: cols 0..63 = s, 64..127 = s2

#pragma unroll
    for (int nb = 0; nb < 8; ++nb) {
        float s0 = 0.f, s1 = 0.f, q0 = 0.f, q1 = 0.f;
#pragma unroll
        for (int msub = 0; msub < 4; ++msub) {
#pragma unroll
            for (int ep = 0; ep < 2; ++ep) {
                int row = row0 + m0 + msub*16 + (lane >> 2) + ep*8;
                int col = n0 + nb*8 + (lane & 3)*2;
                float v0 = acc[msub][nb][ep*2];
                float v1 = acc[msub][nb][ep*2 + 1];
                size_t off = (size_t)row * CH + col;
                if (gate) {
                    float2 g = *reinterpret_cast<const float2*>(gate + off);
                    v0 *= g.x; v1 *= g.y;
                }
                if (out32) *reinterpret_cast<float2*>(out32 + off) = make_float2(v0, v1);
                if (out16) *reinterpret_cast<__half2*>(out16 + off) = __floats2half2_rn(v0, v1);
                s0 += v0; s1 += v1;
                q0 = fmaf(v0, v0, q0); q1 = fmaf(v1, v1, q1);
            }
        }
        if (bnPart) {
#pragma unroll
            for (int off = 16; off >= 4; off >>= 1) {
                s0 += __shfl_down_sync(0xffffffffu, s0, off);
                s1 += __shfl_down_sync(0xffffffffu, s1, off);
                q0 += __shfl_down_sync(0xffffffffu, q0, off);
                q1 += __shfl_down_sync(0xffffffffu, q1, off);
            }
            if (lane < 4) {
                int lc = nb*8 + lane*2;
                red[w*128 + lc]          = s0;
                red[w*128 + lc + 1]      = s1;
                red[w*128 + 64 + lc]     = q0;
                red[w*128 + 64 + lc + 1] = q1;
            }
        }
    }
    if (bnPart) {
        __syncthreads();
        if (tid < CH) {
            int half = tid >> 6;
            int lc   = tid & 63;
            float s = 0.f, q = 0.f;
#pragma unroll
            for (int j = 0; j < 4; ++j) {
                s += red[(2*j + half)*128 + lc];
                q += red[(2*j + half)*128 + 64 + lc];
            }
            bnPart[blockIdx.x*CH + tid]          = s;
            bnPart[128*CH + blockIdx.x*CH + tid] = q;
        }
    }
}

// ======================= BN / elementwise =======================
__global__ void bn_finalize_kernel(const float* __restrict__ gamma, const float* __restrict__ beta)
{
    int c = threadIdx.x;  // 128
    float s = 0.f, s2 = 0.f;
    for (int b = 0; b < 128; ++b) {
        s  += g_part[b*CH + c];
        s2 += g_part[128*CH + b*CH + c];
    }
    const float inv = 1.0f / (float)NPTS;
    float mu = s * inv;
    float var = s2 * inv - mu*mu;
    float sc = gamma[c] * rsqrtf(var + 1e-5f);
    g_scale[c] = sc;
    g_shift[c] = fmaf(-mu, sc, beta[c]);
}
__global__ void ew1_kernel(const float* __restrict__ y, const float* __restrict__ x)
{
    size_t i = (size_t)blockIdx.x * blockDim.x + threadIdx.x;
    float4 yv = reinterpret_cast<const float4*>(y)[i];
    float4 xv = reinterpret_cast<const float4*>(x)[i];
    int cg = (int)(i & 31);
    float4 sc = reinterpret_cast<const float4*>(g_scale)[cg];
    float4 sh = reinterpret_cast<const float4*>(g_shift)[cg];
    float4 r2;
    r2.x = fmaf(yv.x, sc.x, sh.x) + xv.x;
    r2.y = fmaf(yv.y, sc.y, sh.y) + xv.y;
    r2.z = fmaf(yv.z, sc.z, sh.z) + xv.z;
    r2.w = fmaf(yv.w, sc.w, sh.w) + xv.w;
    reinterpret_cast<float4*>(g_R)[i] = r2;
    reinterpret_cast<__half2*>(g_Th)[2*i]   = __floats2half2_rn(fmaxf(r2.x,0.f), fmaxf(r2.y,0.f));
    reinterpret_cast<__half2*>(g_Th)[2*i+1] = __floats2half2_rn(fmaxf(r2.z,0.f), fmaxf(r2.w,0.f));
}
__global__ void ew2_kernel(const float* __restrict__ y, float* __restrict__ out)
{
    size_t i = (size_t)blockIdx.x * blockDim.x + threadIdx.x;
    float4 yv = reinterpret_cast<const float4*>(y)[i];
    float4 rv = reinterpret_cast<const float4*>(g_R)[i];
    int cg = (int)(i & 31);
    float4 sc = reinterpret_cast<const float4*>(g_scale)[cg];
    float4 sh = reinterpret_cast<const float4*>(g_shift)[cg];
    float4 o;
    o.x = fmaxf(fmaf(yv.x, sc.x, sh.x) + rv.x, 0.f);
    o.y = fmaxf(fmaf(yv.y, sc.y, sh.y) + rv.y, 0.f);
    o.z = fmaxf(fmaf(yv.z, sc.z, sh.z) + rv.z, 0.f);
    o.w = fmaxf(fmaf(yv.w, sc.w, sh.w) + rv.w, 0.f);
    reinterpret_cast<float4*>(out)[i] = o;
}

// ======================= launch =======================
extern "C" void kernel_launch(void* const* d_in, const int* in_sizes, int n_in,
                              void* d_out, int out_size)
{
    const float* x      = (const float*)d_in[0];
    const float* Wa1    = (const float*)d_in[1];
    const float* Wv1    = (const float*)d_in[2];
    const float* W5     = (const float*)d_in[3];
    const float* W31    = (const float*)d_in[4];
    const float* W32    = (const float*)d_in[5];
    const float* gamma1 = (const float*)d_in[6];
    const float* beta1  = (const float*)d_in[7];
    const float* gamma2 = (const float*)d_in[8];
    const float* beta2  = (const float*)d_in[9];
    const int*   nbr5   = (const int*)d_in[10];
    const int*   nbr3a  = (const int*)d_in[11];
    const int*   nbr3b  = (const int*)d_in[12];
    float* out = (float*)d_out;

    float *pV, *pY, *pPart;
    __half *pXh, *pAh, *pGh, *pTh, *pW5b, *pW31b, *pW32b, *pWa1b, *pWv1b;
    int *pn5, *pn3a, *pn3b;
    cudaGetSymbolAddress((void**)&pV,  g_V);
    cudaGetSymbolAddress((void**)&pY,  g_Y);
    cudaGetSymbolAddress((void**)&pPart, g_part);
    cudaGetSymbolAddress((void**)&pXh, g_Xh);
    cudaGetSymbolAddress((void**)&pAh, g_Ah);
    cudaGetSymbolAddress((void**)&pGh, g_Gh);
    cudaGetSymbolAddress((void**)&pTh, g_Th);
    cudaGetSymbolAddress((void**)&pW5b, g_W5b);
    cudaGetSymbolAddress((void**)&pW31b, g_W31b);
    cudaGetSymbolAddress((void**)&pW32b, g_W32b);
    cudaGetSymbolAddress((void**)&pWa1b, g_Wa1b);
    cudaGetSymbolAddress((void**)&pWv1b, g_Wv1b);
    cudaGetSymbolAddress((void**)&pn5,  g_nT5);
    cudaGetSymbolAddress((void**)&pn3a, g_nT3a);
    cudaGetSymbolAddress((void**)&pn3b, g_nT3b);

    cudaFuncSetAttribute(tconv_kernel, cudaFuncAttributeMaxDynamicSharedMemorySize, TCONV_SMEM);

    const int tgrid = NPTS / MROWS;       // 128
    const int ewgrid = (NPTS*CH/4) / 256;

    // 1: all weight images   2: neighbor transposes   3: x -> fp16
    wprep_all<<<181*64, 256>>>(W5, W31, W32, Wa1, Wv1, pW5b, pW31b, pW32b, pWa1b, pWv1b);
    ntr_all<<<dim3(6, NPTS/32), 256>>>(nbr5, nbr3a, nbr3b, pn5, pn3a, pn3b);
    cvt_kernel<<<ewgrid, 256>>>(x, pXh);
    // 4-5: 1x1 GEMMs on the HMMA path (identity gather, K=1)
    tconv_kernel<<<tgrid, NT, TCONV_SMEM>>>(pXh, pWa1b, nullptr, 1, nullptr, pAh, nullptr, nullptr);
    tconv_kernel<<<tgrid, NT, TCONV_SMEM>>>(pXh, pWv1b, nullptr, 1, nullptr, nullptr, pV, nullptr);
    // 6: Gh = fp16( conv5(a) * v )  -- gate fused
    tconv_kernel<<<tgrid, NT, TCONV_SMEM>>>(pAh, pW5b, pn5, 125, pV, pGh, nullptr, nullptr);
    // 7-9: conv3a (BN1 partials fused) -> BN1 finalize -> ew1
    tconv_kernel<<<tgrid, NT, TCONV_SMEM>>>(pGh, pW31b, pn3a, 27, nullptr, nullptr, pY, pPart);
    bn_finalize_kernel<<<1, 128>>>(gamma1, beta1);
    ew1_kernel<<<ewgrid, 256>>>(pY, x);
    // 10-12: conv3b (BN2 partials fused) -> BN2 finalize -> ew2
    tconv_kernel<<<tgrid, NT, TCONV_SMEM>>>(pTh, pW32b, pn3b, 27, nullptr, nullptr, pY, pPart);
    bn_finalize_kernel<<<1, 128>>>(gamma2, beta2);
    ew2_kernel<<<ewgrid, 256>>>(pY, out);
}

// round 16
// speedup vs baseline: 1.6086x; 1.0058x over previous
#include <cuda_runtime.h>
#include <cuda_fp16.h>

#define NPTS 32768
#define CH   128
#define NT   256

// ======================= baseline-PTX helpers =======================
__device__ __forceinline__ unsigned smem_to_u32(const void* p) {
    unsigned a;
    asm("{ .reg .u64 t; cvta.to.shared.u64 t, %1; cvt.u32.u64 %0, t; }" : "=r"(a) : "l"(p));
    return a;
}
__device__ __forceinline__ void cp16(unsigned dst, const void* src) {
    asm volatile("cp.async.cg.shared.global [%0], [%1], 16;" :: "r"(dst), "l"(src));
}
#define CP_COMMIT() asm volatile("cp.async.commit_group;" ::: "memory")
#define CP_WAIT(n)  asm volatile("cp.async.wait_group %0;" :: "n"(n) : "memory")

__device__ __forceinline__ void ldsm_x4(unsigned* r, unsigned addr) {
    asm volatile("ldmatrix.sync.aligned.m8n8.x4.shared.b16 {%0,%1,%2,%3}, [%4];"
        : "=r"(r[0]), "=r"(r[1]), "=r"(r[2]), "=r"(r[3]) : "r"(addr));
}
__device__ __forceinline__ void ldsm_x4_t(unsigned* r, unsigned addr) {
    asm volatile("ldmatrix.sync.aligned.m8n8.x4.trans.shared.b16 {%0,%1,%2,%3}, [%4];"
        : "=r"(r[0]), "=r"(r[1]), "=r"(r[2]), "=r"(r[3]) : "r"(addr));
}
__device__ __forceinline__ void mma16816(float* c, const unsigned* a, unsigned b0, unsigned b1) {
    asm volatile("mma.sync.aligned.m16n8k16.row.col.f32.f16.f16.f32 "
        "{%0,%1,%2,%3}, {%4,%5,%6,%7}, {%8,%9}, {%0,%1,%2,%3};"
        : "+f"(c[0]), "+f"(c[1]), "+f"(c[2]), "+f"(c[3])
        : "r"(a[0]), "r"(a[1]), "r"(a[2]), "r"(a[3]), "r"(b0), "r"(b1));
}

// ======================= tconv sizes (full-tap stages, M=256, 8 warps) =====
#define MROWS  256
#define ROWB   272                     // padded row stride (16B-aligned, ldsm-safe)
#define ABUF   (MROWS*ROWB)            // 69632
#define BBUF   (128*ROWB)              // 34816
#define STG    (ABUF + BBUF)           // 104448
#define IDXSZ  1024                    // 256 ints per slot
#define TCONV_SMEM (2*STG + 4*IDXSZ)   // 212992 (1 CTA/SM)
#define GAV_SMEM  (ABUF + 2*BBUF)      // 139264

// ======================= scratch =======================
__device__ __align__(16) float  g_V [NPTS*CH];
__device__ __align__(16) float  g_Y [NPTS*CH];
__device__ __align__(16) float  g_R [NPTS*CH];
__device__ __align__(16) __half g_Xh[NPTS*CH];
__device__ __align__(16) __half g_Ah[NPTS*CH];
__device__ __align__(16) __half g_Gh[NPTS*CH];
__device__ __align__(16) __half g_Th[NPTS*CH];
__device__ __align__(16) __half g_W5b [125*CH*CH];   // fp16 [k][ci][co]
__device__ __align__(16) __half g_W31b[27*CH*CH];
__device__ __align__(16) __half g_W32b[27*CH*CH];
__device__ __align__(16) __half g_Wa1b[CH*CH];
__device__ __align__(16) __half g_Wv1b[CH*CH];
__device__ int g_nT5 [125*NPTS];
__device__ int g_nT3a[27*NPTS];
__device__ int g_nT3b[27*NPTS];
__device__ __align__(16) float g_part[2*128*CH];     // per-CTA BN partials (s | s2)
__device__ __align__(16) float g_scale[CH];
__device__ __align__(16) float g_shift[CH];

// ======================= prep kernels (fused) =======================
__global__ void wprep_all(const float* __restrict__ W5, const float* __restrict__ W31,
                          const float* __restrict__ W32,
                          const float* __restrict__ Wa1, const float* __restrict__ Wv1,
                          __half* __restrict__ o5, __half* __restrict__ o31,
                          __half* __restrict__ o32,
                          __half* __restrict__ oa, __half* __restrict__ ov)
{
    int b = blockIdx.x;
    const float* W; __half* O; int kb;
    if (b < 125*64)      { W = W5;  O = o5;  kb = b; }
    else if (b < 152*64) { W = W31; O = o31; kb = b - 125*64; }
    else if (b < 179*64) { W = W32; O = o32; kb = b - 152*64; }
    else if (b < 180*64) { W = Wa1; O = oa;  kb = b - 179*64; }
    else                 { W = Wv1; O = ov;  kb = b - 180*64; }
    int e = kb * 256 + threadIdx.x;
    O[e] = __float2half_rn(W[e]);
}

__global__ void ntr_all(const int* __restrict__ nbr5, const int* __restrict__ nbr3a,
                        const int* __restrict__ nbr3b,
                        int* __restrict__ n5, int* __restrict__ n3a, int* __restrict__ n3b)
{
    __shared__ int t[32][33];
    int bx = blockIdx.x;
    const int* src; int* dst; int K, k0;
    if (bx < 4)       { src = nbr5;  dst = n5;  K = 125; k0 = bx*32; }
    else if (bx == 4) { src = nbr3a; dst = n3a; K = 27;  k0 = 0; }
    else              { src = nbr3b; dst = n3b; K = 27;  k0 = 0; }
    int i0 = blockIdx.y * 32;
    int tx = threadIdx.x & 31, ty = threadIdx.x >> 5;
#pragma unroll
    for (int r = 0; r < 32; r += 8) {
        int kk = k0 + tx;
        t[ty + r][tx] = (kk < K) ? src[(size_t)(i0 + ty + r) * K + kk] : 0;
    }
    __syncthreads();
#pragma unroll
    for (int r = 0; r < 32; r += 8) {
        int kk = k0 + ty + r;
        if (kk < K) dst[(size_t)kk * NPTS + i0 + tx] = t[tx][ty + r];
    }
}

__global__ void cvt_kernel(const float* __restrict__ in, __half* __restrict__ out)
{
    int i = blockIdx.x * 256 + threadIdx.x;       // float4 units
    float4 v = reinterpret_cast<const float4*>(in)[i];
    reinterpret_cast<__half2*>(out)[2*i]   = __floats2half2_rn(v.x, v.y);
    reinterpret_cast<__half2*>(out)[2*i+1] = __floats2half2_rn(v.z, v.w);
}

// ======================= fused 1x1 GEMM pair: Ah = Xh@Wa, V = Xh@Wv =========
__global__ void __launch_bounds__(NT, 1)
gemm_av_kernel(const __half* __restrict__ Xh,
               const __half* __restrict__ Wa, const __half* __restrict__ Wv,
               __half* __restrict__ Ah, float* __restrict__ V)
{
    extern __shared__ char dsm[];
    const int tid  = threadIdx.x;
    const int lane = tid & 31;
    const int w    = tid >> 5;
    const int row0 = blockIdx.x * MROWS;
    const int m0   = (w >> 1) * 64;
    const int n0   = (w & 1) * 64;
    const unsigned smem = smem_to_u32(dsm);
    const unsigned Ab  = smem;
    const unsigned Bb0 = smem + ABUF;
    const unsigned Bb1 = Bb0 + BBUF;

    // load A tile once + both weight tiles
#pragma unroll
    for (int j = 0; j < 16; ++j) {
        int lin = tid + 256*j;
        int row = lin >> 4;
        int c   = lin & 15;
        cp16(Ab + (unsigned)row*ROWB + (unsigned)c*16u,
             (const char*)(Xh + (size_t)(row0 + row)*CH) + c*16);
    }
#pragma unroll
    for (int j = 0; j < 8; ++j) {
        int lin = tid + 256*j;
        int row = lin >> 4;
        int c   = lin & 15;
        cp16(Bb0 + (unsigned)row*ROWB + (unsigned)c*16u, (const char*)Wa + (size_t)row*256 + c*16);
        cp16(Bb1 + (unsigned)row*ROWB + (unsigned)c*16u, (const char*)Wv + (size_t)row*256 + c*16);
    }
    CP_COMMIT();
    CP_WAIT(0);
    __syncthreads();

    const unsigned lane_off = (unsigned)(lane & 15) * ROWB + (unsigned)(lane >> 4) * 16u;
    float acc[4][8][4];

#pragma unroll
    for (int pass = 0; pass < 2; ++pass) {
        const unsigned Bb = pass ? Bb1 : Bb0;
#pragma unroll
        for (int i = 0; i < 4; ++i)
#pragma unroll
            for (int j = 0; j < 8; ++j)
#pragma unroll
                for (int e = 0; e < 4; ++e) acc[i][j][e] = 0.f;

#pragma unroll
        for (int ks = 0; ks < 8; ++ks) {
            unsigned a[4][4];
            unsigned abase = Ab + (unsigned)m0*ROWB + (unsigned)ks*32u + lane_off;
#pragma unroll
            for (int q = 0; q < 4; ++q) ldsm_x4(a[q], abase + (unsigned)q*16u*ROWB);
            unsigned bbase = Bb + (unsigned)ks*16u*ROWB + (unsigned)n0*2u + lane_off;
            unsigned b[4][4];
#pragma unroll
            for (int p = 0; p < 4; ++p) ldsm_x4_t(b[p], bbase + (unsigned)p*32u);
#pragma unroll
            for (int p = 0; p < 4; ++p) {
#pragma unroll
                for (int q = 0; q < 4; ++q) {
                    mma16816(acc[q][2*p],   a[q], b[p][0], b[p][1]);
                    mma16816(acc[q][2*p+1], a[q], b[p][2], b[p][3]);
                }
            }
        }

#pragma unroll
        for (int msub = 0; msub < 4; ++msub) {
#pragma unroll
            for (int nb = 0; nb < 8; ++nb) {
#pragma unroll
                for (int ep = 0; ep < 2; ++ep) {
                    int row = row0 + m0 + msub*16 + (lane >> 2) + ep*8;
                    int col = n0 + nb*8 + (lane & 3)*2;
                    float v0 = acc[msub][nb][ep*2];
                    float v1 = acc[msub][nb][ep*2 + 1];
                    size_t off = (size_t)row * CH + col;
                    if (pass == 0)
                        *reinterpret_cast<__half2*>(Ah + off) = __floats2half2_rn(v0, v1);
                    else
                        *reinterpret_cast<float2*>(V + off) = make_float2(v0, v1);
                }
            }
        }
    }
}

// ======================= HMMA gather-conv ====================================
// R13 skeleton (coalesced gather, depth-2 prefetch, 2 syncs/tap, smem idx pipe)
// + fused deterministic BN partial reduction (bnPart != null).
__device__ __forceinline__ void issue_tap(
    unsigned smem, const int* __restrict__ idxSlots, int tap, int K,
    const __half* feats, const __half* Wb, const int* nbrT,
    int row0, int tid)
{
    const int buf = tap & 1;
    const unsigned Ab = smem + (unsigned)buf*STG;
    const unsigned Bb = Ab + ABUF;
    const int* slot = idxSlots + (tap & 3) * 256;
    // A: 256 rows x 256B = 4096 chunks; 16 lanes cover one row (coalesced)
#pragma unroll
    for (int j = 0; j < 16; ++j) {
        int lin = tid + 256*j;
        int row = lin >> 4;
        int c   = lin & 15;
        int idx = nbrT ? slot[row] : (row0 + row);
        cp16(Ab + (unsigned)row*ROWB + (unsigned)c*16u,
             (const char*)(feats + (size_t)idx*CH) + c*16);
    }
    // B: 128 rows x 256B = 2048 chunks
    const char* wsrc = (const char*)(Wb + (size_t)tap*(CH*CH));
#pragma unroll
    for (int j = 0; j < 8; ++j) {
        int lin = tid + 256*j;
        int row = lin >> 4;
        int c   = lin & 15;
        cp16(Bb + (unsigned)row*ROWB + (unsigned)c*16u, wsrc + (size_t)row*256 + c*16);
    }
    // idx block for tap+2 -> slot (tap+2)&3 (1KB, 64 chunks)
    if (nbrT && tap + 2 < K && tid < 64) {
        unsigned dst = smem + 2u*STG + (unsigned)((tap + 2) & 3)*IDXSZ + (unsigned)tid*16u;
        cp16(dst, (const char*)(nbrT + (size_t)(tap + 2)*NPTS + row0) + tid*16);
    }
}

__global__ void __launch_bounds__(NT, 1)
tconv_kernel(const __half* __restrict__ feats,
             const __half* __restrict__ Wb,     // [K][128][128] fp16
             const int*    __restrict__ nbrT,   // [K][NPTS] or null
             const int K,
             const float*  __restrict__ gate,   // fp32 or null
             __half* __restrict__ out16,        // or null
             float*  __restrict__ out32,        // or null
             float*  __restrict__ bnPart)       // per-CTA BN partials or null
{
    extern __shared__ char dsm[];
    const int tid  = threadIdx.x;
    const int lane = tid & 31;
    const int w    = tid >> 5;          // 0..7
    const int row0 = blockIdx.x * MROWS;
    const int m0   = (w >> 1) * 64;     // 4 m-groups of 64 rows
    const int n0   = (w & 1) * 64;      // 2 n-groups of 64 cols
    const unsigned smem = smem_to_u32(dsm);
    int* idxSlots = (int*)(dsm + 2*STG);

    // prologue: fill idx slots 0,1 synchronously, then issue taps 0,1
    if (nbrT) {
        idxSlots[tid]       = nbrT[row0 + tid];
        idxSlots[256 + tid] = (K > 1) ? nbrT[(size_t)NPTS + row0 + tid] : 0;
        __syncthreads();
    }
    issue_tap(smem, idxSlots, 0, K, feats, Wb, nbrT, row0, tid);
    CP_COMMIT();
    if (K > 1) {
        issue_tap(smem, idxSlots, 1, K, feats, Wb, nbrT, row0, tid);
        CP_COMMIT();
    }

    float acc[4][8][4];
#pragma unroll
    for (int i = 0; i < 4; ++i)
#pragma unroll
        for (int j = 0; j < 8; ++j)
#pragma unroll
            for (int e = 0; e < 4; ++e) acc[i][j][e] = 0.f;

    const unsigned lane_off = (unsigned)(lane & 15) * ROWB + (unsigned)(lane >> 4) * 16u;

    for (int k = 0; k < K; ++k) {
        const int buf = k & 1;
        if (k + 1 < K) { CP_WAIT(1); } else { CP_WAIT(0); }
        __syncthreads();   // tap k (and its idx slot for k+2) visible to all

        const unsigned Ab = smem + (unsigned)buf*STG;
        const unsigned Bb = Ab + ABUF;

#pragma unroll
        for (int ks = 0; ks < 8; ++ks) {
            unsigned a[4][4];
            unsigned abase = Ab + (unsigned)m0*ROWB + (unsigned)ks*32u + lane_off;
#pragma unroll
            for (int q = 0; q < 4; ++q) ldsm_x4(a[q], abase + (unsigned)q*16u*ROWB);
            unsigned bbase = Bb + (unsigned)ks*16u*ROWB + (unsigned)n0*2u + lane_off;
            unsigned b[4][4];
#pragma unroll
            for (int p = 0; p < 4; ++p) ldsm_x4_t(b[p], bbase + (unsigned)p*32u);
#pragma unroll
            for (int p = 0; p < 4; ++p) {
#pragma unroll
                for (int q = 0; q < 4; ++q) {
                    mma16816(acc[q][2*p],   a[q], b[p][0], b[p][1]);
                    mma16816(acc[q][2*p+1], a[q], b[p][2], b[p][3]);
                }
            }
        }

        __syncthreads();   // all warps done reading buf before refill

        if (k + 2 < K) {
            issue_tap(smem, idxSlots, k + 2, K, feats, Wb, nbrT, row0, tid);
            CP_COMMIT();
        }
    }

    // ===== epilogue: store (+optional gate) and optional fused BN partials ====
    float* red = (float*)dsm;   // [warp][128]: cols 0..63 = s, 64..127 = s2

#pragma unroll
    for (int nb = 0; nb < 8; ++nb) {
        float s0 = 0.f, s1 = 0.f, q0 = 0.f, q1 = 0.f;
#pragma unroll
        for (int msub = 0; msub < 4; ++msub) {
#pragma unroll
            for (int ep = 0; ep < 2; ++ep) {
                int row = row0 + m0 + msub*16 + (lane >> 2) + ep*8;
                int col = n0 + nb*8 + (lane & 3)*2;
                float v0 = acc[msub][nb][ep*2];
                float v1 = acc[msub][nb][ep*2 + 1];
                size_t off = (size_t)row * CH + col;
                if (gate) {
                    float2 g = *reinterpret_cast<const float2*>(gate + off);
                    v0 *= g.x; v1 *= g.y;
                }
                if (out32) *reinterpret_cast<float2*>(out32 + off) = make_float2(v0, v1);
                if (out16) *reinterpret_cast<__half2*>(out16 + off) = __floats2half2_rn(v0, v1);
                s0 += v0; s1 += v1;
                q0 = fmaf(v0, v0, q0); q1 = fmaf(v1, v1, q1);
            }
        }
        if (bnPart) {
#pragma unroll
            for (int off = 16; off >= 4; off >>= 1) {
                s0 += __shfl_down_sync(0xffffffffu, s0, off);
                s1 += __shfl_down_sync(0xffffffffu, s1, off);
                q0 += __shfl_down_sync(0xffffffffu, q0, off);
                q1 += __shfl_down_sync(0xffffffffu, q1, off);
            }
            if (lane < 4) {
                int lc = nb*8 + lane*2;
                red[w*128 + lc]          = s0;
                red[w*128 + lc + 1]      = s1;
                red[w*128 + 64 + lc]     = q0;
                red[w*128 + 64 + lc + 1] = q1;
            }
        }
    }
    if (bnPart) {
        __syncthreads();
        if (tid < CH) {
            int half = tid >> 6;
            int lc   = tid & 63;
            float s = 0.f, q = 0.f;
#pragma unroll
            for (int j = 0; j < 4; ++j) {
                s += red[(2*j + half)*128 + lc];
                q += red[(2*j + half)*128 + 64 + lc];
            }
            bnPart[blockIdx.x*CH + tid]          = s;
            bnPart[128*CH + blockIdx.x*CH + tid] = q;
        }
    }
}

// ======================= BN / elementwise =======================
__global__ void bn_finalize_kernel(const float* __restrict__ gamma, const float* __restrict__ beta)
{
    int c = threadIdx.x;  // 128
    float s = 0.f, s2 = 0.f;
    for (int b = 0; b < 128; ++b) {
        s  += g_part[b*CH + c];
        s2 += g_part[128*CH + b*CH + c];
    }
    const float inv = 1.0f / (float)NPTS;
    float mu = s * inv;
    float var = s2 * inv - mu*mu;
    float sc = gamma[c] * rsqrtf(var + 1e-5f);
    g_scale[c] = sc;
    g_shift[c] = fmaf(-mu, sc, beta[c]);
}
__global__ void ew1_kernel(const float* __restrict__ y, const float* __restrict__ x)
{
    size_t i = (size_t)blockIdx.x * blockDim.x + threadIdx.x;
    float4 yv = reinterpret_cast<const float4*>(y)[i];
    float4 xv = reinterpret_cast<const float4*>(x)[i];
    int cg = (int)(i & 31);
    float4 sc = reinterpret_cast<const float4*>(g_scale)[cg];
    float4 sh = reinterpret_cast<const float4*>(g_shift)[cg];
    float4 r2;
    r2.x = fmaf(yv.x, sc.x, sh.x) + xv.x;
    r2.y = fmaf(yv.y, sc.y, sh.y) + xv.y;
    r2.z = fmaf(yv.z, sc.z, sh.z) + xv.z;
    r2.w = fmaf(yv.w, sc.w, sh.w) + xv.w;
    reinterpret_cast<float4*>(g_R)[i] = r2;
    reinterpret_cast<__half2*>(g_Th)[2*i]   = __floats2half2_rn(fmaxf(r2.x,0.f), fmaxf(r2.y,0.f));
    reinterpret_cast<__half2*>(g_Th)[2*i+1] = __floats2half2_rn(fmaxf(r2.z,0.f), fmaxf(r2.w,0.f));
}
__global__ void ew2_kernel(const float* __restrict__ y, float* __restrict__ out)
{
    size_t i = (size_t)blockIdx.x * blockDim.x + threadIdx.x;
    float4 yv = reinterpret_cast<const float4*>(y)[i];
    float4 rv = reinterpret_cast<const float4*>(g_R)[i];
    int cg = (int)(i & 31);
    float4 sc = reinterpret_cast<const float4*>(g_scale)[cg];
    float4 sh = reinterpret_cast<const float4*>(g_shift)[cg];
    float4 o;
    o.x = fmaxf(fmaf(yv.x, sc.x, sh.x) + rv.x, 0.f);
    o.y = fmaxf(fmaf(yv.y, sc.y, sh.y) + rv.y, 0.f);
    o.z = fmaxf(fmaf(yv.z, sc.z, sh.z) + rv.z, 0.f);
    o.w = fmaxf(fmaf(yv.w, sc.w, sh.w) + rv.w, 0.f);
    reinterpret_cast<float4*>(out)[i] = o;
}

// ======================= launch =======================
extern "C" void kernel_launch(void* const* d_in, const int* in_sizes, int n_in,
                              void* d_out, int out_size)
{
    const float* x      = (const float*)d_in[0];
    const float* Wa1    = (const float*)d_in[1];
    const float* Wv1    = (const float*)d_in[2];
    const float* W5     = (const float*)d_in[3];
    const float* W31    = (const float*)d_in[4];
    const float* W32    = (const float*)d_in[5];
    const float* gamma1 = (const float*)d_in[6];
    const float* beta1  = (const float*)d_in[7];
    const float* gamma2 = (const float*)d_in[8];
    const float* beta2  = (const float*)d_in[9];
    const int*   nbr5   = (const int*)d_in[10];
    const int*   nbr3a  = (const int*)d_in[11];
    const int*   nbr3b  = (const int*)d_in[12];
    float* out = (float*)d_out;

    float *pV, *pY, *pPart;
    __half *pXh, *pAh, *pGh, *pTh, *pW5b, *pW31b, *pW32b, *pWa1b, *pWv1b;
    int *pn5, *pn3a, *pn3b;
    cudaGetSymbolAddress((void**)&pV,  g_V);
    cudaGetSymbolAddress((void**)&pY,  g_Y);
    cudaGetSymbolAddress((void**)&pPart, g_part);
    cudaGetSymbolAddress((void**)&pXh, g_Xh);
    cudaGetSymbolAddress((void**)&pAh, g_Ah);
    cudaGetSymbolAddress((void**)&pGh, g_Gh);
    cudaGetSymbolAddress((void**)&pTh, g_Th);
    cudaGetSymbolAddress((void**)&pW5b, g_W5b);
    cudaGetSymbolAddress((void**)&pW31b, g_W31b);
    cudaGetSymbolAddress((void**)&pW32b, g_W32b);
    cudaGetSymbolAddress((void**)&pWa1b, g_Wa1b);
    cudaGetSymbolAddress((void**)&pWv1b, g_Wv1b);
    cudaGetSymbolAddress((void**)&pn5,  g_nT5);
    cudaGetSymbolAddress((void**)&pn3a, g_nT3a);
    cudaGetSymbolAddress((void**)&pn3b, g_nT3b);

    cudaFuncSetAttribute(tconv_kernel, cudaFuncAttributeMaxDynamicSharedMemorySize, TCONV_SMEM);
    cudaFuncSetAttribute(gemm_av_kernel, cudaFuncAttributeMaxDynamicSharedMemorySize, GAV_SMEM);

    const int tgrid = NPTS / MROWS;       // 128
    const int ewgrid = (NPTS*CH/4) / 256;

    // 1: all weight images   2: neighbor transposes   3: x -> fp16
    wprep_all<<<181*64, 256>>>(W5, W31, W32, Wa1, Wv1, pW5b, pW31b, pW32b, pWa1b, pWv1b);
    ntr_all<<<dim3(6, NPTS/32), 256>>>(nbr5, nbr3a, nbr3b, pn5, pn3a, pn3b);
    cvt_kernel<<<ewgrid, 256>>>(x, pXh);
    // 4: both 1x1 GEMMs in one launch, sharing the Xh tile
    gemm_av_kernel<<<tgrid, NT, GAV_SMEM>>>(pXh, pWa1b, pWv1b, pAh, pV);
    // 5: Gh = fp16( conv5(a) * v )  -- gate fused
    tconv_kernel<<<tgrid, NT, TCONV_SMEM>>>(pAh, pW5b, pn5, 125, pV, pGh, nullptr, nullptr);
    // 6-8: conv3a (BN1 partials fused) -> BN1 finalize -> ew1
    tconv_kernel<<<tgrid, NT, TCONV_SMEM>>>(pGh, pW31b, pn3a, 27, nullptr, nullptr, pY, pPart);
    bn_finalize_kernel<<<1, 128>>>(gamma1, beta1);
    ew1_kernel<<<ewgrid, 256>>>(pY, x);
    // 9-11: conv3b (BN2 partials fused) -> BN2 finalize -> ew2
    tconv_kernel<<<tgrid, NT, TCONV_SMEM>>>(pTh, pW32b, pn3b, 27, nullptr, nullptr, pY, pPart);
    bn_finalize_kernel<<<1, 128>>>(gamma2, beta2);
    ew2_kernel<<<ewgrid, 256>>>(pY, out);
}